// round 1
// baseline (speedup 1.0000x reference)
#include <cuda_runtime.h>
#include <cstdint>

#define NN 50000
#define EE 400000
#define FF 128
#define HH 8
#define HDIM 16
#define RBFN 100

// ---------------- scratch (static device allocations; no cudaMalloc) ----------------
__device__ float g_xn[(size_t)NN * FF];          // 25.6 MB
__device__ float g_qkv[(size_t)NN * 640];        // 128 MB  : [q(128) | k(128) | v(384)]
__device__ float g_vp[(size_t)NN * 3 * 384];     // 230 MB  : vec @ Wvec^T
__device__ float g_dkdv[(size_t)EE * 512];       // 819 MB  : [dk(128) | dv(384)] per edge
__device__ float g_xagg[(size_t)NN * FF];        // 25.6 MB
__device__ float g_vagg[(size_t)NN * 384];       // 76.8 MB
__device__ float g_o[(size_t)NN * 384];          // 76.8 MB
__device__ float g_Wqkv[640 * 128];
__device__ float g_bqkv[640];
__device__ float g_Wdkv[512 * RBFN];
__device__ float g_bdkv[512];

// ---------------- weight concat prep ----------------
__global__ void prep_weights(const float* __restrict__ Wq, const float* __restrict__ Wk,
                             const float* __restrict__ Wv, const float* __restrict__ bq,
                             const float* __restrict__ bk, const float* __restrict__ bv,
                             const float* __restrict__ Wdk, const float* __restrict__ Wdv,
                             const float* __restrict__ bdk, const float* __restrict__ bdv) {
    int i = blockIdx.x * blockDim.x + threadIdx.x;
    if (i < 640 * 128) {
        int r = i / 128, c = i % 128;
        float v;
        if (r < 128)      v = Wq[r * 128 + c];
        else if (r < 256) v = Wk[(r - 128) * 128 + c];
        else              v = Wv[(r - 256) * 128 + c];
        g_Wqkv[i] = v;
    }
    if (i < 640)
        g_bqkv[i] = (i < 128) ? bq[i] : (i < 256) ? bk[i - 128] : bv[i - 256];
    if (i < 512 * RBFN) {
        int r = i / RBFN, c = i % RBFN;
        g_Wdkv[i] = (r < 128) ? Wdk[r * RBFN + c] : Wdv[(r - 128) * RBFN + c];
    }
    if (i < 512)
        g_bdkv[i] = (i < 128) ? bdk[i] : bdv[i - 128];
}

// ---------------- LayerNorm ----------------
__global__ void ln_kernel(const float* __restrict__ x, const float* __restrict__ w,
                          const float* __restrict__ b) {
    int n = blockIdx.x;
    int f = threadIdx.x;  // 128 threads
    float v = x[(size_t)n * FF + f];
    __shared__ float red1[4], red2[4];
    float s = v;
    #pragma unroll
    for (int o = 16; o > 0; o >>= 1) s += __shfl_xor_sync(0xffffffffu, s, o);
    if ((f & 31) == 0) red1[f >> 5] = s;
    __syncthreads();
    float mean = (red1[0] + red1[1] + red1[2] + red1[3]) * (1.0f / FF);
    float c = v - mean;
    float s2 = c * c;
    #pragma unroll
    for (int o = 16; o > 0; o >>= 1) s2 += __shfl_xor_sync(0xffffffffu, s2, o);
    if ((f & 31) == 0) red2[f >> 5] = s2;
    __syncthreads();
    float var = (red2[0] + red2[1] + red2[2] + red2[3]) * (1.0f / FF);
    g_xn[(size_t)n * FF + f] = c * rsqrtf(var + 1e-5f) * w[f] + b[f];
}

// ---------------- tiled fp32 SGEMM: C[M,N] = act(A[M,K] @ B[N,K]^T + bias) ----------------
#define BM 128
#define BN 128
#define BK 8
#define TM 8
#define TN 8
__global__ __launch_bounds__(256) void sgemm_bias_act(
    const float* __restrict__ A, const float* __restrict__ B,
    const float* __restrict__ bias, float* __restrict__ C,
    int M, int Nn, int K, int act) {
    __shared__ float As[BK][BM];
    __shared__ float Bs[BK][BN];
    int tid = threadIdx.x;
    int row0 = blockIdx.y * BM;
    int col0 = blockIdx.x * BN;
    int tx = tid & 15;   // 0..15 (cols)
    int ty = tid >> 4;   // 0..15 (rows)
    int ldRow = tid >> 1;           // 0..127
    int ldCol = (tid & 1) * 4;      // 0 or 4
    float acc[TM][TN];
    #pragma unroll
    for (int i = 0; i < TM; i++)
        #pragma unroll
        for (int j = 0; j < TN; j++) acc[i][j] = 0.f;

    for (int k0 = 0; k0 < K; k0 += BK) {
        int m = row0 + ldRow;
        #pragma unroll
        for (int i = 0; i < 4; i++) {
            int k = k0 + ldCol + i;
            As[ldCol + i][ldRow] = (m < M && k < K) ? A[(size_t)m * K + k] : 0.f;
        }
        int nidx = col0 + ldRow;
        #pragma unroll
        for (int i = 0; i < 4; i++) {
            int k = k0 + ldCol + i;
            Bs[ldCol + i][ldRow] = (nidx < Nn && k < K) ? B[(size_t)nidx * K + k] : 0.f;
        }
        __syncthreads();
        #pragma unroll
        for (int k = 0; k < BK; k++) {
            float ra[TM], rb[TN];
            #pragma unroll
            for (int i = 0; i < TM; i++) ra[i] = As[k][ty * TM + i];
            #pragma unroll
            for (int j = 0; j < TN; j++) rb[j] = Bs[k][tx * TN + j];
            #pragma unroll
            for (int i = 0; i < TM; i++)
                #pragma unroll
                for (int j = 0; j < TN; j++) acc[i][j] += ra[i] * rb[j];
        }
        __syncthreads();
    }
    #pragma unroll
    for (int i = 0; i < TM; i++) {
        int m = row0 + ty * TM + i;
        if (m >= M) continue;
        #pragma unroll
        for (int j = 0; j < TN; j++) {
            int n = col0 + tx * TN + j;
            if (n >= Nn) continue;
            float v = acc[i][j] + bias[n];
            if (act) v = v / (1.f + __expf(-v));  // silu
            C[(size_t)m * Nn + n] = v;
        }
    }
}

// ---------------- fused edge kernel ----------------
__global__ void edge_kernel(const int* __restrict__ ei, const float* __restrict__ r_ij,
                            const float* __restrict__ d_ij, const float* __restrict__ vec) {
    int e = blockIdx.x;
    int f = threadIdx.x;  // 0..127 ; head h = f>>4, dim d = f&15
    int src = ei[e];
    int dst = ei[EE + e];

    float q  = g_qkv[(size_t)dst * 640 + f];
    float kk = g_qkv[(size_t)src * 640 + 128 + f];
    float dk = g_dkdv[(size_t)e * 512 + f];
    float p = q * kk * dk;
    #pragma unroll
    for (int o = 8; o > 0; o >>= 1) p += __shfl_xor_sync(0xffffffffu, p, o, 16);
    // silu + cutoff
    float attn = p / (1.f + __expf(-p));
    float r = r_ij[e];
    float cut = 0.5f * (__cosf(r * 0.52359877559829887f) + 1.f) * (r < 6.0f ? 1.f : 0.f);
    attn *= cut;

    int h = f >> 4, d = f & 15;
    size_t vb  = (size_t)src * 640 + 256 + (size_t)h * 48;
    size_t dvb = (size_t)e * 512 + 128 + (size_t)h * 48;
    float xm  = g_qkv[vb + d]      * g_dkdv[dvb + d]      * attn;
    float v1m = g_qkv[vb + 16 + d] * g_dkdv[dvb + 16 + d];
    float v2m = g_qkv[vb + 32 + d] * g_dkdv[dvb + 32 + d];

    atomicAdd(&g_xagg[(size_t)dst * FF + f], xm);

    float d0 = d_ij[(size_t)e * 3 + 0];
    float d1 = d_ij[(size_t)e * 3 + 1];
    float d2 = d_ij[(size_t)e * 3 + 2];
    float ds[3] = {d0, d1, d2};
    #pragma unroll
    for (int s = 0; s < 3; s++) {
        float vm = vec[(size_t)src * 384 + s * 128 + f] * v1m + v2m * ds[s];
        atomicAdd(&g_vagg[((size_t)dst * 3 + s) * FF + f], vm);
    }
}

// ---------------- final epilogue ----------------
__global__ void final_kernel(float* __restrict__ out) {
    int n = blockIdx.x;
    int f = threadIdx.x;  // 128
    size_t ob = (size_t)n * 384;
    float o1 = g_o[ob + f], o2 = g_o[ob + 128 + f], o3 = g_o[ob + 256 + f];
    size_t vb = (size_t)n * 1152;
    float vd = 0.f;
    #pragma unroll
    for (int s = 0; s < 3; s++)
        vd += g_vp[vb + s * 384 + f] * g_vp[vb + s * 384 + 128 + f];
    out[(size_t)n * FF + f] = vd * o2 + o3;
    #pragma unroll
    for (int s = 0; s < 3; s++) {
        float v3 = g_vp[vb + s * 384 + 256 + f];
        out[(size_t)NN * FF + ((size_t)n * 3 + s) * FF + f] =
            v3 * o1 + g_vagg[((size_t)n * 3 + s) * FF + f];
    }
}

// ---------------- launch ----------------
extern "C" void kernel_launch(void* const* d_in, const int* in_sizes, int n_in,
                              void* d_out, int out_size) {
    const float* x    = (const float*)d_in[0];
    const float* vec  = (const float*)d_in[1];
    const int*   ei   = (const int*)d_in[2];
    const float* r_ij = (const float*)d_in[3];
    const float* f_ij = (const float*)d_in[4];
    const float* d_ij = (const float*)d_in[5];
    const float* ln_w = (const float*)d_in[6];
    const float* ln_b = (const float*)d_in[7];
    const float* Wq   = (const float*)d_in[8];
    const float* bq   = (const float*)d_in[9];
    const float* Wk   = (const float*)d_in[10];
    const float* bk   = (const float*)d_in[11];
    const float* Wv   = (const float*)d_in[12];
    const float* bv   = (const float*)d_in[13];
    const float* Wvec = (const float*)d_in[14];
    const float* bvec = (const float*)d_in[15];
    const float* Wo   = (const float*)d_in[16];
    const float* bo   = (const float*)d_in[17];
    const float* Wdk  = (const float*)d_in[18];
    const float* bdk  = (const float*)d_in[19];
    const float* Wdv  = (const float*)d_in[20];
    const float* bdv  = (const float*)d_in[21];
    float* out = (float*)d_out;

    void *pxn, *pqkv, *pvp, *pdkdv, *pxagg, *pvagg, *po, *pWqkv, *pbqkv, *pWdkv, *pbdkv;
    cudaGetSymbolAddress(&pxn, g_xn);
    cudaGetSymbolAddress(&pqkv, g_qkv);
    cudaGetSymbolAddress(&pvp, g_vp);
    cudaGetSymbolAddress(&pdkdv, g_dkdv);
    cudaGetSymbolAddress(&pxagg, g_xagg);
    cudaGetSymbolAddress(&pvagg, g_vagg);
    cudaGetSymbolAddress(&po, g_o);
    cudaGetSymbolAddress(&pWqkv, g_Wqkv);
    cudaGetSymbolAddress(&pbqkv, g_bqkv);
    cudaGetSymbolAddress(&pWdkv, g_Wdkv);
    cudaGetSymbolAddress(&pbdkv, g_bdkv);

    // 1. weight concat
    prep_weights<<<(640 * 128 + 255) / 256, 256>>>(Wq, Wk, Wv, bq, bk, bv, Wdk, Wdv, bdk, bdv);
    // 2. LayerNorm
    ln_kernel<<<NN, 128>>>(x, ln_w, ln_b);
    // 3. qkv = xn @ Wqkv^T  (50000 x 640, K=128)
    {
        dim3 grid((640 + BN - 1) / BN, (NN + BM - 1) / BM);
        sgemm_bias_act<<<grid, 256>>>((const float*)pxn, (const float*)pWqkv,
                                      (const float*)pbqkv, (float*)pqkv, NN, 640, 128, 0);
    }
    // 4. vp = vec(3N x 128) @ Wvec^T  (150000 x 384)
    {
        dim3 grid((384 + BN - 1) / BN, (3 * NN + BM - 1) / BM);
        sgemm_bias_act<<<grid, 256>>>(vec, Wvec, bvec, (float*)pvp, 3 * NN, 384, 128, 0);
    }
    // 5. dkdv = silu(f_ij @ Wdkv^T)  (400000 x 512, K=100)
    {
        dim3 grid((512 + BN - 1) / BN, (EE + BM - 1) / BM);
        sgemm_bias_act<<<grid, 256>>>(f_ij, (const float*)pWdkv,
                                      (const float*)pbdkv, (float*)pdkdv, EE, 512, RBFN, 1);
    }
    // 6. zero aggregation buffers
    cudaMemsetAsync(pxagg, 0, (size_t)NN * FF * sizeof(float));
    cudaMemsetAsync(pvagg, 0, (size_t)NN * 384 * sizeof(float));
    // 7. edge message + scatter
    edge_kernel<<<EE, 128>>>(ei, r_ij, d_ij, vec);
    // 8. o = x_agg @ Wo^T  (50000 x 384)
    {
        dim3 grid((384 + BN - 1) / BN, (NN + BM - 1) / BM);
        sgemm_bias_act<<<grid, 256>>>((const float*)pxagg, Wo, bo, (float*)po, NN, 384, 128, 0);
    }
    // 9. epilogue -> out = [dx (N*128) | dvec (N*3*128)]
    final_kernel<<<NN, 128>>>(out);
}

// round 2
// speedup vs baseline: 1.4004x; 1.4004x over previous
#include <cuda_runtime.h>
#include <cstdint>

#define NN 50000
#define EE 400000
#define FF 128
#define HH 8
#define HDIM 16
#define RBFN 100

// ---------------- scratch (static device allocations; no cudaMalloc) ----------------
__device__ float g_xn[(size_t)NN * FF];
__device__ float g_qkv[(size_t)NN * 640];        // [q(128) | k(128) | v(384)]
__device__ float g_vp[(size_t)NN * 3 * 384];
__device__ float g_dkdv[(size_t)EE * 512];       // [dk(128) | dv(384)]
__device__ float g_xagg[(size_t)NN * FF];
__device__ float g_vagg[(size_t)NN * 384];
__device__ float g_o[(size_t)NN * 384];
__device__ float g_Wqkv[640 * 128];
__device__ float g_bqkv[640];
__device__ float g_Wdkv[512 * RBFN];
__device__ float g_bdkv[512];

// ---------------- vector reduction to global (sm_90+/sm_103a) ----------------
__device__ __forceinline__ void red_add_v4(float* p, float4 v) {
    asm volatile("red.global.add.v4.f32 [%0], {%1, %2, %3, %4};"
                 :: "l"(p), "f"(v.x), "f"(v.y), "f"(v.z), "f"(v.w) : "memory");
}

// ---------------- weight concat prep ----------------
__global__ void prep_weights(const float* __restrict__ Wq, const float* __restrict__ Wk,
                             const float* __restrict__ Wv, const float* __restrict__ bq,
                             const float* __restrict__ bk, const float* __restrict__ bv,
                             const float* __restrict__ Wdk, const float* __restrict__ Wdv,
                             const float* __restrict__ bdk, const float* __restrict__ bdv) {
    int i = blockIdx.x * blockDim.x + threadIdx.x;
    if (i < 640 * 128) {
        int r = i / 128, c = i % 128;
        float v;
        if (r < 128)      v = Wq[r * 128 + c];
        else if (r < 256) v = Wk[(r - 128) * 128 + c];
        else              v = Wv[(r - 256) * 128 + c];
        g_Wqkv[i] = v;
    }
    if (i < 640)
        g_bqkv[i] = (i < 128) ? bq[i] : (i < 256) ? bk[i - 128] : bv[i - 256];
    if (i < 512 * RBFN) {
        int r = i / RBFN, c = i % RBFN;
        g_Wdkv[i] = (r < 128) ? Wdk[r * RBFN + c] : Wdv[(r - 128) * RBFN + c];
    }
    if (i < 512)
        g_bdkv[i] = (i < 128) ? bdk[i] : bdv[i - 128];
}

// ---------------- LayerNorm ----------------
__global__ void ln_kernel(const float* __restrict__ x, const float* __restrict__ w,
                          const float* __restrict__ b) {
    int n = blockIdx.x;
    int f = threadIdx.x;  // 128 threads
    float v = x[(size_t)n * FF + f];
    __shared__ float red1[4], red2[4];
    float s = v;
    #pragma unroll
    for (int o = 16; o > 0; o >>= 1) s += __shfl_xor_sync(0xffffffffu, s, o);
    if ((f & 31) == 0) red1[f >> 5] = s;
    __syncthreads();
    float mean = (red1[0] + red1[1] + red1[2] + red1[3]) * (1.0f / FF);
    float c = v - mean;
    float s2 = c * c;
    #pragma unroll
    for (int o = 16; o > 0; o >>= 1) s2 += __shfl_xor_sync(0xffffffffu, s2, o);
    if ((f & 31) == 0) red2[f >> 5] = s2;
    __syncthreads();
    float var = (red2[0] + red2[1] + red2[2] + red2[3]) * (1.0f / FF);
    g_xn[(size_t)n * FF + f] = c * rsqrtf(var + 1e-5f) * w[f] + b[f];
}

// ---------------- SGEMM v2: double-buffered, BK=16, float4 everywhere ----------------
#define BM 128
#define BN 128
#define BK 16
#define TM 8
#define TN 8

__device__ __forceinline__ float4 ld_g4(const float* __restrict__ P, int r, int c,
                                        int R, int Kd) {
    float4 v = make_float4(0.f, 0.f, 0.f, 0.f);
    if (r < R) {
        if (c + 4 <= Kd) {
            v = *(const float4*)(P + (size_t)r * Kd + c);
        } else {
            const float* row = P + (size_t)r * Kd;
            if (c < Kd)     v.x = row[c];
            if (c + 1 < Kd) v.y = row[c + 1];
            if (c + 2 < Kd) v.z = row[c + 2];
            if (c + 3 < Kd) v.w = row[c + 3];
        }
    }
    return v;
}

__global__ __launch_bounds__(256, 2) void sgemm_v2(
    const float* __restrict__ A, const float* __restrict__ B,
    const float* __restrict__ bias, float* __restrict__ C,
    int M, int Nn, int K, int act) {
    __shared__ float As[2][BK][BM];
    __shared__ float Bs[2][BK][BN];
    int tid = threadIdx.x;
    int row0 = blockIdx.y * BM;
    int col0 = blockIdx.x * BN;
    int tx = tid & 15;   // 0..15 (cols)
    int ty = tid >> 4;   // 0..15 (rows)
    int ldRow = tid >> 1;        // 0..127
    int ldCol = (tid & 1) * 8;   // 0 or 8

    float acc[TM][TN];
    #pragma unroll
    for (int i = 0; i < TM; i++)
        #pragma unroll
        for (int j = 0; j < TN; j++) acc[i][j] = 0.f;

    int nT = (K + BK - 1) / BK;

    // preload tile 0
    {
        float4 a0 = ld_g4(A, row0 + ldRow, ldCol,     M,  K);
        float4 a1 = ld_g4(A, row0 + ldRow, ldCol + 4, M,  K);
        float4 b0 = ld_g4(B, col0 + ldRow, ldCol,     Nn, K);
        float4 b1 = ld_g4(B, col0 + ldRow, ldCol + 4, Nn, K);
        As[0][ldCol + 0][ldRow] = a0.x; As[0][ldCol + 1][ldRow] = a0.y;
        As[0][ldCol + 2][ldRow] = a0.z; As[0][ldCol + 3][ldRow] = a0.w;
        As[0][ldCol + 4][ldRow] = a1.x; As[0][ldCol + 5][ldRow] = a1.y;
        As[0][ldCol + 6][ldRow] = a1.z; As[0][ldCol + 7][ldRow] = a1.w;
        Bs[0][ldCol + 0][ldRow] = b0.x; Bs[0][ldCol + 1][ldRow] = b0.y;
        Bs[0][ldCol + 2][ldRow] = b0.z; Bs[0][ldCol + 3][ldRow] = b0.w;
        Bs[0][ldCol + 4][ldRow] = b1.x; Bs[0][ldCol + 5][ldRow] = b1.y;
        Bs[0][ldCol + 6][ldRow] = b1.z; Bs[0][ldCol + 7][ldRow] = b1.w;
    }
    __syncthreads();

    for (int t = 0; t < nT; t++) {
        int cur = t & 1;
        bool more = (t + 1 < nT);
        float4 pa0, pa1, pb0, pb1;
        if (more) {
            int k0 = (t + 1) * BK;
            pa0 = ld_g4(A, row0 + ldRow, k0 + ldCol,     M,  K);
            pa1 = ld_g4(A, row0 + ldRow, k0 + ldCol + 4, M,  K);
            pb0 = ld_g4(B, col0 + ldRow, k0 + ldCol,     Nn, K);
            pb1 = ld_g4(B, col0 + ldRow, k0 + ldCol + 4, Nn, K);
        }
        #pragma unroll
        for (int k = 0; k < BK; k++) {
            float4 ra0 = *(const float4*)&As[cur][k][ty * TM];
            float4 ra1 = *(const float4*)&As[cur][k][ty * TM + 4];
            float4 rb0 = *(const float4*)&Bs[cur][k][tx * TN];
            float4 rb1 = *(const float4*)&Bs[cur][k][tx * TN + 4];
            float ra[TM] = {ra0.x, ra0.y, ra0.z, ra0.w, ra1.x, ra1.y, ra1.z, ra1.w};
            float rb[TN] = {rb0.x, rb0.y, rb0.z, rb0.w, rb1.x, rb1.y, rb1.z, rb1.w};
            #pragma unroll
            for (int i = 0; i < TM; i++)
                #pragma unroll
                for (int j = 0; j < TN; j++) acc[i][j] += ra[i] * rb[j];
        }
        if (more) {
            int nxt = cur ^ 1;
            As[nxt][ldCol + 0][ldRow] = pa0.x; As[nxt][ldCol + 1][ldRow] = pa0.y;
            As[nxt][ldCol + 2][ldRow] = pa0.z; As[nxt][ldCol + 3][ldRow] = pa0.w;
            As[nxt][ldCol + 4][ldRow] = pa1.x; As[nxt][ldCol + 5][ldRow] = pa1.y;
            As[nxt][ldCol + 6][ldRow] = pa1.z; As[nxt][ldCol + 7][ldRow] = pa1.w;
            Bs[nxt][ldCol + 0][ldRow] = pb0.x; Bs[nxt][ldCol + 1][ldRow] = pb0.y;
            Bs[nxt][ldCol + 2][ldRow] = pb0.z; Bs[nxt][ldCol + 3][ldRow] = pb0.w;
            Bs[nxt][ldCol + 4][ldRow] = pb1.x; Bs[nxt][ldCol + 5][ldRow] = pb1.y;
            Bs[nxt][ldCol + 6][ldRow] = pb1.z; Bs[nxt][ldCol + 7][ldRow] = pb1.w;
            __syncthreads();
        }
    }

    // epilogue (Nn is always a multiple of 128 in our calls; M may be ragged)
    #pragma unroll
    for (int i = 0; i < TM; i++) {
        int m = row0 + ty * TM + i;
        if (m >= M) continue;
        int n = col0 + tx * TN;
        float4 o0, o1;
        float* po[8] = {&o0.x, &o0.y, &o0.z, &o0.w, &o1.x, &o1.y, &o1.z, &o1.w};
        #pragma unroll
        for (int j = 0; j < TN; j++) {
            float v = acc[i][j] + bias[n + j];
            if (act) v = v / (1.f + __expf(-v));
            *po[j] = v;
        }
        *(float4*)(C + (size_t)m * Nn + n)     = o0;
        *(float4*)(C + (size_t)m * Nn + n + 4) = o1;
    }
}

// ---------------- fused edge kernel: one warp per edge, float4 + red.v4 ----------------
__global__ __launch_bounds__(256) void edge_kernel(const int* __restrict__ ei,
                                                   const float* __restrict__ r_ij,
                                                   const float* __restrict__ d_ij,
                                                   const float* __restrict__ vec) {
    int gw = (blockIdx.x * blockDim.x + threadIdx.x) >> 5;
    if (gw >= EE) return;
    int lane = threadIdx.x & 31;
    int e = gw;
    int src = ei[e];
    int dst = ei[EE + e];

    float4 q  = ((const float4*)(g_qkv + (size_t)dst * 640))[lane];
    float4 kk = ((const float4*)(g_qkv + (size_t)src * 640 + 128))[lane];
    float4 dk = ((const float4*)(g_dkdv + (size_t)e * 512))[lane];
    float p = q.x * kk.x * dk.x + q.y * kk.y * dk.y + q.z * kk.z * dk.z + q.w * kk.w * dk.w;
    p += __shfl_xor_sync(0xffffffffu, p, 1);
    p += __shfl_xor_sync(0xffffffffu, p, 2);
    // silu + cutoff
    float attn = p / (1.f + __expf(-p));
    float r = r_ij[e];
    float cut = (r < 6.0f) ? 0.5f * (__cosf(r * 0.52359877559829887f) + 1.f) : 0.f;
    attn *= cut;

    int h = lane >> 2;
    int d4 = (lane & 3) * 4;
    const float* vb  = g_qkv  + (size_t)src * 640 + 256 + h * 48 + d4;
    const float* dvb = g_dkdv + (size_t)e * 512 + 128 + h * 48 + d4;
    float4 v0 = *(const float4*)vb;
    float4 v1 = *(const float4*)(vb + 16);
    float4 v2 = *(const float4*)(vb + 32);
    float4 w0 = *(const float4*)dvb;
    float4 w1 = *(const float4*)(dvb + 16);
    float4 w2 = *(const float4*)(dvb + 32);

    float4 xm  = make_float4(v0.x * w0.x * attn, v0.y * w0.y * attn,
                             v0.z * w0.z * attn, v0.w * w0.w * attn);
    float4 v1m = make_float4(v1.x * w1.x, v1.y * w1.y, v1.z * w1.z, v1.w * w1.w);
    float4 v2m = make_float4(v2.x * w2.x, v2.y * w2.y, v2.z * w2.z, v2.w * w2.w);

    red_add_v4(g_xagg + (size_t)dst * FF + lane * 4, xm);

    float dsx = d_ij[(size_t)e * 3 + 0];
    float dsy = d_ij[(size_t)e * 3 + 1];
    float dsz = d_ij[(size_t)e * 3 + 2];
    float ds[3] = {dsx, dsy, dsz};
    #pragma unroll
    for (int s = 0; s < 3; s++) {
        float4 vv = ((const float4*)(vec + (size_t)src * 384 + s * 128))[lane];
        float4 vm = make_float4(vv.x * v1m.x + v2m.x * ds[s],
                                vv.y * v1m.y + v2m.y * ds[s],
                                vv.z * v1m.z + v2m.z * ds[s],
                                vv.w * v1m.w + v2m.w * ds[s]);
        red_add_v4(g_vagg + (size_t)dst * 384 + s * 128 + lane * 4, vm);
    }
}

// ---------------- final epilogue ----------------
__global__ void final_kernel(float* __restrict__ out) {
    int n = blockIdx.x;
    int f = threadIdx.x;  // 128
    size_t ob = (size_t)n * 384;
    float o1 = g_o[ob + f], o2 = g_o[ob + 128 + f], o3 = g_o[ob + 256 + f];
    size_t vb = (size_t)n * 1152;
    float vd = 0.f;
    #pragma unroll
    for (int s = 0; s < 3; s++)
        vd += g_vp[vb + s * 384 + f] * g_vp[vb + s * 384 + 128 + f];
    out[(size_t)n * FF + f] = vd * o2 + o3;
    #pragma unroll
    for (int s = 0; s < 3; s++) {
        float v3 = g_vp[vb + s * 384 + 256 + f];
        out[(size_t)NN * FF + ((size_t)n * 3 + s) * FF + f] =
            v3 * o1 + g_vagg[((size_t)n * 3 + s) * FF + f];
    }
}

// ---------------- launch ----------------
extern "C" void kernel_launch(void* const* d_in, const int* in_sizes, int n_in,
                              void* d_out, int out_size) {
    const float* x    = (const float*)d_in[0];
    const float* vec  = (const float*)d_in[1];
    const int*   ei   = (const int*)d_in[2];
    const float* r_ij = (const float*)d_in[3];
    const float* f_ij = (const float*)d_in[4];
    const float* d_ij = (const float*)d_in[5];
    const float* ln_w = (const float*)d_in[6];
    const float* ln_b = (const float*)d_in[7];
    const float* Wq   = (const float*)d_in[8];
    const float* bq   = (const float*)d_in[9];
    const float* Wk   = (const float*)d_in[10];
    const float* bk   = (const float*)d_in[11];
    const float* Wv   = (const float*)d_in[12];
    const float* bv   = (const float*)d_in[13];
    const float* Wvec = (const float*)d_in[14];
    const float* bvec = (const float*)d_in[15];
    const float* Wo   = (const float*)d_in[16];
    const float* bo   = (const float*)d_in[17];
    const float* Wdk  = (const float*)d_in[18];
    const float* bdk  = (const float*)d_in[19];
    const float* Wdv  = (const float*)d_in[20];
    const float* bdv  = (const float*)d_in[21];
    float* out = (float*)d_out;

    void *pxn, *pqkv, *pvp, *pdkdv, *pxagg, *pvagg, *po, *pWqkv, *pbqkv, *pWdkv, *pbdkv;
    cudaGetSymbolAddress(&pxn, g_xn);
    cudaGetSymbolAddress(&pqkv, g_qkv);
    cudaGetSymbolAddress(&pvp, g_vp);
    cudaGetSymbolAddress(&pdkdv, g_dkdv);
    cudaGetSymbolAddress(&pxagg, g_xagg);
    cudaGetSymbolAddress(&pvagg, g_vagg);
    cudaGetSymbolAddress(&po, g_o);
    cudaGetSymbolAddress(&pWqkv, g_Wqkv);
    cudaGetSymbolAddress(&pbqkv, g_bqkv);
    cudaGetSymbolAddress(&pWdkv, g_Wdkv);
    cudaGetSymbolAddress(&pbdkv, g_bdkv);

    // 1. weight concat
    prep_weights<<<(640 * 128 + 255) / 256, 256>>>(Wq, Wk, Wv, bq, bk, bv, Wdk, Wdv, bdk, bdv);
    // 2. LayerNorm
    ln_kernel<<<NN, 128>>>(x, ln_w, ln_b);
    // 3. qkv = xn @ Wqkv^T  (50000 x 640, K=128)
    {
        dim3 grid(640 / BN, (NN + BM - 1) / BM);
        sgemm_v2<<<grid, 256>>>((const float*)pxn, (const float*)pWqkv,
                                (const float*)pbqkv, (float*)pqkv, NN, 640, 128, 0);
    }
    // 4. vp = vec(3N x 128) @ Wvec^T  (150000 x 384)
    {
        dim3 grid(384 / BN, (3 * NN + BM - 1) / BM);
        sgemm_v2<<<grid, 256>>>(vec, Wvec, bvec, (float*)pvp, 3 * NN, 384, 128, 0);
    }
    // 5. dkdv = silu(f_ij @ Wdkv^T)  (400000 x 512, K=100)
    {
        dim3 grid(512 / BN, (EE + BM - 1) / BM);
        sgemm_v2<<<grid, 256>>>(f_ij, (const float*)pWdkv,
                                (const float*)pbdkv, (float*)pdkdv, EE, 512, RBFN, 1);
    }
    // 6. zero aggregation buffers
    cudaMemsetAsync(pxagg, 0, (size_t)NN * FF * sizeof(float));
    cudaMemsetAsync(pvagg, 0, (size_t)NN * 384 * sizeof(float));
    // 7. edge message + scatter (warp per edge)
    edge_kernel<<<EE / 8, 256>>>(ei, r_ij, d_ij, vec);
    // 8. o = x_agg @ Wo^T  (50000 x 384)
    {
        dim3 grid(384 / BN, (NN + BM - 1) / BM);
        sgemm_v2<<<grid, 256>>>((const float*)pxagg, Wo, bo, (float*)po, NN, 384, 128, 0);
    }
    // 9. epilogue -> out = [dx (N*128) | dvec (N*3*128)]
    final_kernel<<<NN, 128>>>(out);
}

// round 5
// speedup vs baseline: 1.9048x; 1.3602x over previous
#include <cuda_runtime.h>
#include <cuda_bf16.h>
#include <cstdint>

#define NN 50000
#define EE 400000
#define FF 128
#define RBFN 100

// ---------------- scratch (static device allocations; no cudaMalloc) ----------------
__device__ float g_qkv[(size_t)NN * 640];        // [q(128) | k(128) | v(384)]
__device__ float g_vp[(size_t)NN * 3 * 384];
__device__ float g_dkdv[(size_t)EE * 512];       // [dk(128) | dv(384)]
__device__ float g_xagg[(size_t)NN * FF];
__device__ float g_vagg[(size_t)NN * 384];
__device__ float g_o[(size_t)NN * 384];
__device__ float g_Wqkv[640 * 128];
__device__ float g_bqkv[640];
__device__ float g_Wdkv[512 * RBFN];
__device__ float g_bdkv[512];
// bf16 hi/lo split buffers: [R, 256] = [hi(128) | lo(128)]
__device__ __nv_bfloat16 g_xn2[(size_t)NN * 256];
__device__ __nv_bfloat16 g_vec2[(size_t)3 * NN * 256];
__device__ __nv_bfloat16 g_fij2[(size_t)EE * 256];
__device__ __nv_bfloat16 g_xagg2[(size_t)NN * 256];
__device__ __nv_bfloat16 g_Wqkv2[640 * 256];
__device__ __nv_bfloat16 g_Wvec2[384 * 256];
__device__ __nv_bfloat16 g_Wdkv2[512 * 256];
__device__ __nv_bfloat16 g_Wo2[384 * 256];

// ---------------- helpers ----------------
__device__ __forceinline__ uint32_t smem_u32(const void* p) {
    uint32_t a;
    asm("{ .reg .u64 t; cvta.to.shared.u64 t, %1; cvt.u32.u64 %0, t; }" : "=r"(a) : "l"(p));
    return a;
}
__device__ __forceinline__ void cp_async16(uint32_t dst, const void* src, uint32_t src_bytes) {
    asm volatile("cp.async.cg.shared.global [%0], [%1], 16, %2;"
                 :: "r"(dst), "l"(src), "r"(src_bytes) : "memory");
}
#define CP_COMMIT() asm volatile("cp.async.commit_group;" ::: "memory")
#define CP_WAIT1()  asm volatile("cp.async.wait_group 1;" ::: "memory")
#define CP_WAIT0()  asm volatile("cp.async.wait_group 0;" ::: "memory")

__device__ __forceinline__ void ldm_x4(uint32_t& r0, uint32_t& r1, uint32_t& r2, uint32_t& r3,
                                       uint32_t addr) {
    asm volatile("ldmatrix.sync.aligned.m8n8.x4.shared.b16 {%0,%1,%2,%3}, [%4];"
                 : "=r"(r0), "=r"(r1), "=r"(r2), "=r"(r3) : "r"(addr));
}
__device__ __forceinline__ void ldm_x2(uint32_t& r0, uint32_t& r1, uint32_t addr) {
    asm volatile("ldmatrix.sync.aligned.m8n8.x2.shared.b16 {%0,%1}, [%2];"
                 : "=r"(r0), "=r"(r1) : "r"(addr));
}
__device__ __forceinline__ void mma_bf16(float* c, const uint32_t* a, const uint32_t* b) {
    asm volatile("mma.sync.aligned.m16n8k16.row.col.f32.bf16.bf16.f32 "
                 "{%0,%1,%2,%3}, {%4,%5,%6,%7}, {%8,%9}, {%0,%1,%2,%3};"
                 : "+f"(c[0]), "+f"(c[1]), "+f"(c[2]), "+f"(c[3])
                 : "r"(a[0]), "r"(a[1]), "r"(a[2]), "r"(a[3]), "r"(b[0]), "r"(b[1]));
}
__device__ __forceinline__ void red_add_v4(float* p, float4 v) {
    asm volatile("red.global.add.v4.f32 [%0], {%1, %2, %3, %4};"
                 :: "l"(p), "f"(v.x), "f"(v.y), "f"(v.z), "f"(v.w) : "memory");
}

// ---------------- weight concat prep ----------------
__global__ void prep_weights(const float* __restrict__ Wq, const float* __restrict__ Wk,
                             const float* __restrict__ Wv, const float* __restrict__ bq,
                             const float* __restrict__ bk, const float* __restrict__ bv,
                             const float* __restrict__ Wdk, const float* __restrict__ Wdv,
                             const float* __restrict__ bdk, const float* __restrict__ bdv) {
    int i = blockIdx.x * blockDim.x + threadIdx.x;
    if (i < 640 * 128) {
        int r = i / 128, c = i % 128;
        float v;
        if (r < 128)      v = Wq[r * 128 + c];
        else if (r < 256) v = Wk[(r - 128) * 128 + c];
        else              v = Wv[(r - 256) * 128 + c];
        g_Wqkv[i] = v;
    }
    if (i < 640)
        g_bqkv[i] = (i < 128) ? bq[i] : (i < 256) ? bk[i - 128] : bv[i - 256];
    if (i < 512 * RBFN) {
        int r = i / RBFN, c = i % RBFN;
        g_Wdkv[i] = (r < 128) ? Wdk[r * RBFN + c] : Wdv[(r - 128) * RBFN + c];
    }
    if (i < 512)
        g_bdkv[i] = (i < 128) ? bdk[i] : bdv[i - 128];
}

// ---------------- fp32 -> bf16 hi/lo conversion ----------------
__global__ void cvt_hilo(const float* __restrict__ src, __nv_bfloat16* __restrict__ dst,
                         int R, int K) {
    int idx = blockIdx.x * blockDim.x + threadIdx.x;
    int row = idx >> 7, k = idx & 127;
    if (row >= R) return;
    float v = (k < K) ? src[(size_t)row * K + k] : 0.f;
    __nv_bfloat16 hi = __float2bfloat16(v);
    float lo = v - __bfloat162float(hi);
    dst[(size_t)row * 256 + k] = hi;
    dst[(size_t)row * 256 + 128 + k] = __float2bfloat16(lo);
}

// ---------------- LayerNorm (fused hi/lo output) ----------------
__global__ void ln_kernel(const float* __restrict__ x, const float* __restrict__ w,
                          const float* __restrict__ b) {
    int n = blockIdx.x;
    int f = threadIdx.x;  // 128 threads
    float v = x[(size_t)n * FF + f];
    __shared__ float red1[4], red2[4];
    float s = v;
    #pragma unroll
    for (int o = 16; o > 0; o >>= 1) s += __shfl_xor_sync(0xffffffffu, s, o);
    if ((f & 31) == 0) red1[f >> 5] = s;
    __syncthreads();
    float mean = (red1[0] + red1[1] + red1[2] + red1[3]) * (1.0f / FF);
    float c = v - mean;
    float s2 = c * c;
    #pragma unroll
    for (int o = 16; o > 0; o >>= 1) s2 += __shfl_xor_sync(0xffffffffu, s2, o);
    if ((f & 31) == 0) red2[f >> 5] = s2;
    __syncthreads();
    float var = (red2[0] + red2[1] + red2[2] + red2[3]) * (1.0f / FF);
    float y = c * rsqrtf(var + 1e-5f) * w[f] + b[f];
    __nv_bfloat16 hi = __float2bfloat16(y);
    float lo = y - __bfloat162float(hi);
    g_xn2[(size_t)n * 256 + f] = hi;
    g_xn2[(size_t)n * 256 + 128 + f] = __float2bfloat16(lo);
}

// ---------------- HMMA bf16 GEMM with 3-term hi/lo compensation ----------------
// C = A @ B^T where A ~ a_hi + a_lo, B ~ b_hi + b_lo (each [rows,256] = [hi|lo]).
// 12 k-tiles of 32: kt 0-3: hi*hi, kt 4-7: lo*hi, kt 8-11: hi*lo  (lo*lo ~2^-18 dropped).
#define SPITCH 40   // bf16 elements per smem row (32 + 8 pad) -> 80B pitch
#define NKT 12

__global__ __launch_bounds__(256, 2) void hmma_gemm(
    const __nv_bfloat16* __restrict__ A2, const __nv_bfloat16* __restrict__ B2,
    const float* __restrict__ bias, float* __restrict__ C, int M, int Nn, int act) {
    __shared__ __align__(16) __nv_bfloat16 sA[2][128 * SPITCH];
    __shared__ __align__(16) __nv_bfloat16 sB[2][128 * SPITCH];

    int tid = threadIdx.x;
    int wid = tid >> 5, lane = tid & 31;
    int wm = wid & 1, wn = wid >> 1;          // warp grid 2 x 4
    int row0 = blockIdx.y * 128;
    int col0 = blockIdx.x * 128;

    uint32_t sA_base[2] = {smem_u32(sA[0]), smem_u32(sA[1])};
    uint32_t sB_base[2] = {smem_u32(sB[0]), smem_u32(sB[1])};

    float acc[4][4][4];
    #pragma unroll
    for (int i = 0; i < 4; i++)
        #pragma unroll
        for (int j = 0; j < 4; j++)
            #pragma unroll
            for (int k = 0; k < 4; k++) acc[i][j][k] = 0.f;

    // k-tile -> (A k-offset, B k-offset) in the [hi(0..127)|lo(128..255)] layout
    auto prefetch = [&](int kt) {
        int buf = kt & 1;
        int aOff = (kt < 4) ? kt * 32 : (kt < 8) ? 128 + (kt - 4) * 32 : (kt - 8) * 32;
        int bOff = (kt < 8) ? (kt & 3) * 32 : 128 + (kt - 8) * 32;
        #pragma unroll
        for (int i = 0; i < 2; i++) {
            int idx = tid + i * 256;        // 0..511
            int r = idx >> 2;               // 0..127
            int ch = idx & 3;               // 16B chunk
            uint32_t soff = (uint32_t)(r * SPITCH + ch * 8) * 2;
            uint32_t valid = (row0 + r < M) ? 16u : 0u;
            cp_async16(sA_base[buf] + soff,
                       A2 + (size_t)(row0 + r) * 256 + aOff + ch * 8, valid);
            cp_async16(sB_base[buf] + soff,
                       B2 + (size_t)(col0 + r) * 256 + bOff + ch * 8, 16u);
        }
        CP_COMMIT();
    };

    prefetch(0);
    #pragma unroll 1
    for (int kt = 0; kt < NKT; kt++) {
        if (kt + 1 < NKT) { prefetch(kt + 1); CP_WAIT1(); }
        else              { CP_WAIT0(); }
        __syncthreads();
        int buf = kt & 1;
        #pragma unroll
        for (int ks = 0; ks < 32; ks += 16) {
            uint32_t a[4][4], b[4][2];
            #pragma unroll
            for (int mi = 0; mi < 4; mi++) {
                int r = wm * 64 + mi * 16 + (lane & 15);
                int c = ks + (lane >> 4) * 8;
                ldm_x4(a[mi][0], a[mi][1], a[mi][2], a[mi][3],
                       sA_base[buf] + (uint32_t)(r * SPITCH + c) * 2);
            }
            #pragma unroll
            for (int ni = 0; ni < 4; ni++) {
                int r = wn * 32 + ni * 8 + (lane & 7);
                int c = ks + ((lane >> 3) & 1) * 8;
                ldm_x2(b[ni][0], b[ni][1],
                       sB_base[buf] + (uint32_t)(r * SPITCH + c) * 2);
            }
            #pragma unroll
            for (int mi = 0; mi < 4; mi++)
                #pragma unroll
                for (int ni = 0; ni < 4; ni++)
                    mma_bf16(acc[mi][ni], a[mi], b[ni]);
        }
        __syncthreads();
    }

    // epilogue: bias + optional silu, direct float2 stores
    #pragma unroll
    for (int ni = 0; ni < 4; ni++) {
        int n = col0 + wn * 32 + ni * 8 + (lane & 3) * 2;
        float b0 = bias[n], b1 = bias[n + 1];
        #pragma unroll
        for (int mi = 0; mi < 4; mi++) {
            int m = row0 + wm * 64 + mi * 16 + (lane >> 2);
            float v0 = acc[mi][ni][0] + b0;
            float v1 = acc[mi][ni][1] + b1;
            float v2 = acc[mi][ni][2] + b0;
            float v3 = acc[mi][ni][3] + b1;
            if (act) {
                v0 = v0 / (1.f + __expf(-v0));
                v1 = v1 / (1.f + __expf(-v1));
                v2 = v2 / (1.f + __expf(-v2));
                v3 = v3 / (1.f + __expf(-v3));
            }
            if (m < M)     *(float2*)(C + (size_t)m * Nn + n)       = make_float2(v0, v1);
            if (m + 8 < M) *(float2*)(C + (size_t)(m + 8) * Nn + n) = make_float2(v2, v3);
        }
    }
}

// ---------------- fused edge kernel: one warp per edge, float4 + red.v4 ----------------
__global__ __launch_bounds__(256) void edge_kernel(const int* __restrict__ ei,
                                                   const float* __restrict__ r_ij,
                                                   const float* __restrict__ d_ij,
                                                   const float* __restrict__ vec) {
    int gw = (blockIdx.x * blockDim.x + threadIdx.x) >> 5;
    if (gw >= EE) return;
    int lane = threadIdx.x & 31;
    int e = gw;
    int src = ei[e];
    int dst = ei[EE + e];

    float4 q  = ((const float4*)(g_qkv + (size_t)dst * 640))[lane];
    float4 kk = ((const float4*)(g_qkv + (size_t)src * 640 + 128))[lane];
    float4 dk = ((const float4*)(g_dkdv + (size_t)e * 512))[lane];
    float p = q.x * kk.x * dk.x + q.y * kk.y * dk.y + q.z * kk.z * dk.z + q.w * kk.w * dk.w;
    p += __shfl_xor_sync(0xffffffffu, p, 1);
    p += __shfl_xor_sync(0xffffffffu, p, 2);
    float attn = p / (1.f + __expf(-p));
    float r = r_ij[e];
    float cut = (r < 6.0f) ? 0.5f * (__cosf(r * 0.52359877559829887f) + 1.f) : 0.f;
    attn *= cut;

    int h = lane >> 2;
    int d4 = (lane & 3) * 4;
    const float* vb  = g_qkv  + (size_t)src * 640 + 256 + h * 48 + d4;
    const float* dvb = g_dkdv + (size_t)e * 512 + 128 + h * 48 + d4;
    float4 v0 = *(const float4*)vb;
    float4 v1 = *(const float4*)(vb + 16);
    float4 v2 = *(const float4*)(vb + 32);
    float4 w0 = *(const float4*)dvb;
    float4 w1 = *(const float4*)(dvb + 16);
    float4 w2 = *(const float4*)(dvb + 32);

    float4 xm  = make_float4(v0.x * w0.x * attn, v0.y * w0.y * attn,
                             v0.z * w0.z * attn, v0.w * w0.w * attn);
    float4 v1m = make_float4(v1.x * w1.x, v1.y * w1.y, v1.z * w1.z, v1.w * w1.w);
    float4 v2m = make_float4(v2.x * w2.x, v2.y * w2.y, v2.z * w2.z, v2.w * w2.w);

    red_add_v4(g_xagg + (size_t)dst * FF + lane * 4, xm);

    float dsx = d_ij[(size_t)e * 3 + 0];
    float dsy = d_ij[(size_t)e * 3 + 1];
    float dsz = d_ij[(size_t)e * 3 + 2];
    float ds[3] = {dsx, dsy, dsz};
    #pragma unroll
    for (int s = 0; s < 3; s++) {
        float4 vv = ((const float4*)(vec + (size_t)src * 384 + s * 128))[lane];
        float4 vm = make_float4(vv.x * v1m.x + v2m.x * ds[s],
                                vv.y * v1m.y + v2m.y * ds[s],
                                vv.z * v1m.z + v2m.z * ds[s],
                                vv.w * v1m.w + v2m.w * ds[s]);
        red_add_v4(g_vagg + (size_t)dst * 384 + s * 128 + lane * 4, vm);
    }
}

// ---------------- final epilogue ----------------
__global__ void final_kernel(float* __restrict__ out) {
    int n = blockIdx.x;
    int f = threadIdx.x;  // 128
    size_t ob = (size_t)n * 384;
    float o1 = g_o[ob + f], o2 = g_o[ob + 128 + f], o3 = g_o[ob + 256 + f];
    size_t vb = (size_t)n * 1152;
    float vd = 0.f;
    #pragma unroll
    for (int s = 0; s < 3; s++)
        vd += g_vp[vb + s * 384 + f] * g_vp[vb + s * 384 + 128 + f];
    out[(size_t)n * FF + f] = vd * o2 + o3;
    #pragma unroll
    for (int s = 0; s < 3; s++) {
        float v3 = g_vp[vb + s * 384 + 256 + f];
        out[(size_t)NN * FF + ((size_t)n * 3 + s) * FF + f] =
            v3 * o1 + g_vagg[((size_t)n * 3 + s) * FF + f];
    }
}

// ---------------- launch ----------------
extern "C" void kernel_launch(void* const* d_in, const int* in_sizes, int n_in,
                              void* d_out, int out_size) {
    const float* x    = (const float*)d_in[0];
    const float* vec  = (const float*)d_in[1];
    const int*   ei   = (const int*)d_in[2];
    const float* r_ij = (const float*)d_in[3];
    const float* f_ij = (const float*)d_in[4];
    const float* d_ij = (const float*)d_in[5];
    const float* ln_w = (const float*)d_in[6];
    const float* ln_b = (const float*)d_in[7];
    const float* Wq   = (const float*)d_in[8];
    const float* bq   = (const float*)d_in[9];
    const float* Wk   = (const float*)d_in[10];
    const float* bk   = (const float*)d_in[11];
    const float* Wv   = (const float*)d_in[12];
    const float* bv   = (const float*)d_in[13];
    const float* Wvec = (const float*)d_in[14];
    const float* bvec = (const float*)d_in[15];
    const float* Wo   = (const float*)d_in[16];
    const float* bo   = (const float*)d_in[17];
    const float* Wdk  = (const float*)d_in[18];
    const float* bdk  = (const float*)d_in[19];
    const float* Wdv  = (const float*)d_in[20];
    const float* bdv  = (const float*)d_in[21];
    float* out = (float*)d_out;

    void *pqkv, *pvp, *pdkdv, *pxagg, *pvagg, *po, *pWqkv, *pbqkv, *pWdkv, *pbdkv;
    void *pxn2, *pvec2, *pfij2, *pxagg2, *pWqkv2, *pWvec2, *pWdkv2, *pWo2;
    cudaGetSymbolAddress(&pqkv, g_qkv);
    cudaGetSymbolAddress(&pvp, g_vp);
    cudaGetSymbolAddress(&pdkdv, g_dkdv);
    cudaGetSymbolAddress(&pxagg, g_xagg);
    cudaGetSymbolAddress(&pvagg, g_vagg);
    cudaGetSymbolAddress(&po, g_o);
    cudaGetSymbolAddress(&pWqkv, g_Wqkv);
    cudaGetSymbolAddress(&pbqkv, g_bqkv);
    cudaGetSymbolAddress(&pWdkv, g_Wdkv);
    cudaGetSymbolAddress(&pbdkv, g_bdkv);
    cudaGetSymbolAddress(&pxn2, g_xn2);
    cudaGetSymbolAddress(&pvec2, g_vec2);
    cudaGetSymbolAddress(&pfij2, g_fij2);
    cudaGetSymbolAddress(&pxagg2, g_xagg2);
    cudaGetSymbolAddress(&pWqkv2, g_Wqkv2);
    cudaGetSymbolAddress(&pWvec2, g_Wvec2);
    cudaGetSymbolAddress(&pWdkv2, g_Wdkv2);
    cudaGetSymbolAddress(&pWo2, g_Wo2);

    // 1. weight concat + conversions
    prep_weights<<<(640 * 128 + 255) / 256, 256>>>(Wq, Wk, Wv, bq, bk, bv, Wdk, Wdv, bdk, bdv);
    cvt_hilo<<<(640 * 128 + 255) / 256, 256>>>((const float*)pWqkv, (__nv_bfloat16*)pWqkv2, 640, 128);
    cvt_hilo<<<(512 * 128 + 255) / 256, 256>>>((const float*)pWdkv, (__nv_bfloat16*)pWdkv2, 512, RBFN);
    cvt_hilo<<<(384 * 128 + 255) / 256, 256>>>(Wvec, (__nv_bfloat16*)pWvec2, 384, 128);
    cvt_hilo<<<(384 * 128 + 255) / 256, 256>>>(Wo, (__nv_bfloat16*)pWo2, 384, 128);
    // 2. LayerNorm (writes hi/lo directly)
    ln_kernel<<<NN, 128>>>(x, ln_w, ln_b);
    // 3. activation conversions
    cvt_hilo<<<(3 * NN * 128 + 255) / 256, 256>>>(vec, (__nv_bfloat16*)pvec2, 3 * NN, 128);
    cvt_hilo<<<((size_t)EE * 128 + 255) / 256, 256>>>(f_ij, (__nv_bfloat16*)pfij2, EE, RBFN);
    // 4. qkv = xn @ Wqkv^T  (50000 x 640)
    {
        dim3 grid(640 / 128, (NN + 127) / 128);
        hmma_gemm<<<grid, 256>>>((const __nv_bfloat16*)pxn2, (const __nv_bfloat16*)pWqkv2,
                                 (const float*)pbqkv, (float*)pqkv, NN, 640, 0);
    }
    // 5. vp = vec @ Wvec^T  (150000 x 384)
    {
        dim3 grid(384 / 128, (3 * NN + 127) / 128);
        hmma_gemm<<<grid, 256>>>((const __nv_bfloat16*)pvec2, (const __nv_bfloat16*)pWvec2,
                                 bvec, (float*)pvp, 3 * NN, 384, 0);
    }
    // 6. dkdv = silu(f_ij @ Wdkv^T)  (400000 x 512)
    {
        dim3 grid(512 / 128, EE / 128);
        hmma_gemm<<<grid, 256>>>((const __nv_bfloat16*)pfij2, (const __nv_bfloat16*)pWdkv2,
                                 (const float*)pbdkv, (float*)pdkdv, EE, 512, 1);
    }
    // 7. zero aggregation buffers
    cudaMemsetAsync(pxagg, 0, (size_t)NN * FF * sizeof(float));
    cudaMemsetAsync(pvagg, 0, (size_t)NN * 384 * sizeof(float));
    // 8. edge message + scatter
    edge_kernel<<<EE / 8, 256>>>(ei, r_ij, d_ij, vec);
    // 9. convert x_agg, then o = x_agg @ Wo^T  (50000 x 384)
    cvt_hilo<<<(NN * 128 + 255) / 256, 256>>>((const float*)pxagg, (__nv_bfloat16*)pxagg2, NN, 128);
    {
        dim3 grid(384 / 128, (NN + 127) / 128);
        hmma_gemm<<<grid, 256>>>((const __nv_bfloat16*)pxagg2, (const __nv_bfloat16*)pWo2,
                                 bo, (float*)po, NN, 384, 0);
    }
    // 10. epilogue
    final_kernel<<<NN, 128>>>(out);
}

// round 6
// speedup vs baseline: 1.9637x; 1.0309x over previous
#include <cuda_runtime.h>
#include <cuda_bf16.h>
#include <cstdint>

#define NN 50000
#define EE 400000
#define FF 128
#define RBFN 100

// ---------------- scratch (static device allocations; no cudaMalloc) ----------------
__device__ float g_qkv[(size_t)NN * 640];        // [q(128) | k(128) | v(384)]
__device__ float g_vp[(size_t)NN * 3 * 384];
__device__ float g_dkdv[(size_t)EE * 512];       // [dk(128) | dv(384)]
__device__ float g_xagg[(size_t)NN * FF];
__device__ float g_vagg[(size_t)NN * 384];
__device__ float g_o[(size_t)NN * 384];
__device__ float g_bqkv[640];
__device__ float g_bdkv[512];
// bf16 hi/lo split buffers: [R, 256] = [hi(128) | lo(128)]
__device__ __nv_bfloat16 g_xn2[(size_t)NN * 256];
__device__ __nv_bfloat16 g_vec2[(size_t)3 * NN * 256];
__device__ __nv_bfloat16 g_fij2[(size_t)EE * 256];
__device__ __nv_bfloat16 g_xagg2[(size_t)NN * 256];
__device__ __nv_bfloat16 g_Wqkv2[640 * 256];
__device__ __nv_bfloat16 g_Wvec2[384 * 256];
__device__ __nv_bfloat16 g_Wdkv2[512 * 256];
__device__ __nv_bfloat16 g_Wo2[384 * 256];

// ---------------- helpers ----------------
__device__ __forceinline__ uint32_t smem_u32(const void* p) {
    uint32_t a;
    asm("{ .reg .u64 t; cvta.to.shared.u64 t, %1; cvt.u32.u64 %0, t; }" : "=r"(a) : "l"(p));
    return a;
}
__device__ __forceinline__ void cp_async16(uint32_t dst, const void* src, uint32_t src_bytes) {
    asm volatile("cp.async.cg.shared.global [%0], [%1], 16, %2;"
                 :: "r"(dst), "l"(src), "r"(src_bytes) : "memory");
}
#define CP_COMMIT() asm volatile("cp.async.commit_group;" ::: "memory")
#define CP_WAIT1()  asm volatile("cp.async.wait_group 1;" ::: "memory")

__device__ __forceinline__ void ldm_x4(uint32_t& r0, uint32_t& r1, uint32_t& r2, uint32_t& r3,
                                       uint32_t addr) {
    asm volatile("ldmatrix.sync.aligned.m8n8.x4.shared.b16 {%0,%1,%2,%3}, [%4];"
                 : "=r"(r0), "=r"(r1), "=r"(r2), "=r"(r3) : "r"(addr));
}
__device__ __forceinline__ void mma_bf16(float* c, const uint32_t* a, const uint32_t* b) {
    asm volatile("mma.sync.aligned.m16n8k16.row.col.f32.bf16.bf16.f32 "
                 "{%0,%1,%2,%3}, {%4,%5,%6,%7}, {%8,%9}, {%0,%1,%2,%3};"
                 : "+f"(c[0]), "+f"(c[1]), "+f"(c[2]), "+f"(c[3])
                 : "r"(a[0]), "r"(a[1]), "r"(a[2]), "r"(a[3]), "r"(b[0]), "r"(b[1]));
}
__device__ __forceinline__ void red_add_v4(float* p, float4 v) {
    asm volatile("red.global.add.v4.f32 [%0], {%1, %2, %3, %4};"
                 :: "l"(p), "f"(v.x), "f"(v.y), "f"(v.z), "f"(v.w) : "memory");
}
__device__ __forceinline__ void wr_hilo(__nv_bfloat16* dst, size_t row, int col, float v) {
    __nv_bfloat16 hi = __float2bfloat16(v);
    float lo = v - __bfloat162float(hi);
    dst[row * 256 + col] = hi;
    dst[row * 256 + 128 + col] = __float2bfloat16(lo);
}

// ---------------- fused weight prep: concat + hi/lo split in one kernel ----------------
__global__ void prep_all(const float* __restrict__ Wq, const float* __restrict__ Wk,
                         const float* __restrict__ Wv, const float* __restrict__ bq,
                         const float* __restrict__ bk, const float* __restrict__ bv,
                         const float* __restrict__ Wdk, const float* __restrict__ Wdv,
                         const float* __restrict__ bdk, const float* __restrict__ bdv,
                         const float* __restrict__ Wvec, const float* __restrict__ Wo) {
    int i = blockIdx.x * blockDim.x + threadIdx.x;
    int r = i >> 7, c = i & 127;
    if (i < 640 * 128) {
        float v = (r < 128) ? Wq[r * 128 + c]
                : (r < 256) ? Wk[(r - 128) * 128 + c]
                            : Wv[(r - 256) * 128 + c];
        wr_hilo(g_Wqkv2, r, c, v);
    }
    if (i < 512 * 128) {
        float v = (c < RBFN) ? ((r < 128) ? Wdk[r * RBFN + c] : Wdv[(r - 128) * RBFN + c]) : 0.f;
        wr_hilo(g_Wdkv2, r, c, v);
    }
    if (i < 384 * 128) {
        wr_hilo(g_Wvec2, r, c, Wvec[r * 128 + c]);
        wr_hilo(g_Wo2, r, c, Wo[r * 128 + c]);
    }
    if (i < 640)
        g_bqkv[i] = (i < 128) ? bq[i] : (i < 256) ? bk[i - 128] : bv[i - 256];
    if (i < 512)
        g_bdkv[i] = (i < 128) ? bdk[i] : bdv[i - 128];
}

// ---------------- fp32 -> bf16 hi/lo conversion (activations) ----------------
__global__ void cvt_hilo(const float* __restrict__ src, __nv_bfloat16* __restrict__ dst,
                         int R, int K) {
    int idx = blockIdx.x * blockDim.x + threadIdx.x;
    int row = idx >> 7, k = idx & 127;
    if (row >= R) return;
    float v = (k < K) ? src[(size_t)row * K + k] : 0.f;
    wr_hilo(dst, row, k, v);
}

// ---------------- LayerNorm (fused hi/lo output) ----------------
__global__ void ln_kernel(const float* __restrict__ x, const float* __restrict__ w,
                          const float* __restrict__ b) {
    int n = blockIdx.x;
    int f = threadIdx.x;  // 128 threads
    float v = x[(size_t)n * FF + f];
    __shared__ float red1[4], red2[4];
    float s = v;
    #pragma unroll
    for (int o = 16; o > 0; o >>= 1) s += __shfl_xor_sync(0xffffffffu, s, o);
    if ((f & 31) == 0) red1[f >> 5] = s;
    __syncthreads();
    float mean = (red1[0] + red1[1] + red1[2] + red1[3]) * (1.0f / FF);
    float c = v - mean;
    float s2 = c * c;
    #pragma unroll
    for (int o = 16; o > 0; o >>= 1) s2 += __shfl_xor_sync(0xffffffffu, s2, o);
    if ((f & 31) == 0) red2[f >> 5] = s2;
    __syncthreads();
    float var = (red2[0] + red2[1] + red2[2] + red2[3]) * (1.0f / FF);
    float y = c * rsqrtf(var + 1e-5f) * w[f] + b[f];
    wr_hilo(g_xn2, n, f, y);
}

// ---------------- HMMA bf16 GEMM v3: 3-stage pipeline, 1 sync/kt, B via ldmatrix.x4 ----
// C = A @ B^T, 3-term hi/lo: kt 0-3 hi*hi, 4-7 lo*hi, 8-11 hi*lo.
#define SPITCH 40   // bf16 elements per smem row (32 + 8 pad) -> 80B pitch
#define NKT 12
#define STAGE_BYTES (128 * SPITCH * 2)          // 10240 per operand
#define HMMA_SMEM (3 * 2 * STAGE_BYTES)          // 61440

__global__ __launch_bounds__(256, 2) void hmma_gemm(
    const __nv_bfloat16* __restrict__ A2, const __nv_bfloat16* __restrict__ B2,
    const float* __restrict__ bias, float* __restrict__ C, int M, int Nn, int act) {
    extern __shared__ char dynsmem[];

    int tid = threadIdx.x;
    int wid = tid >> 5, lane = tid & 31;
    int wm = wid & 1, wn = wid >> 1;          // warp grid 2m x 4n
    int row0 = blockIdx.y * 128;
    int col0 = blockIdx.x * 128;

    uint32_t sA_base[3], sB_base[3];
    #pragma unroll
    for (int s = 0; s < 3; s++) {
        sA_base[s] = smem_u32(dynsmem + s * 2 * STAGE_BYTES);
        sB_base[s] = sA_base[s] + STAGE_BYTES;
    }

    float acc[4][4][4];
    #pragma unroll
    for (int i = 0; i < 4; i++)
        #pragma unroll
        for (int j = 0; j < 4; j++)
            #pragma unroll
            for (int k = 0; k < 4; k++) acc[i][j][k] = 0.f;

    // k-tile -> (A k-offset, B k-offset) in the [hi(0..127)|lo(128..255)] layout
    auto prefetch = [&](int kt) {
        int buf = kt % 3;
        int aOff = ((kt >= 4 && kt < 8) ? 128 : 0) + (kt & 3) * 32;
        int bOff = ((kt >= 8) ? 128 : 0) + (kt & 3) * 32;
        #pragma unroll
        for (int i = 0; i < 2; i++) {
            int idx = tid + i * 256;        // 0..511
            int r = idx >> 2;               // 0..127
            int ch = idx & 3;               // 16B chunk
            uint32_t soff = (uint32_t)(r * SPITCH + ch * 8) * 2;
            uint32_t valid = (row0 + r < M) ? 16u : 0u;
            cp_async16(sA_base[buf] + soff,
                       A2 + (size_t)(row0 + r) * 256 + aOff + ch * 8, valid);
            cp_async16(sB_base[buf] + soff,
                       B2 + (size_t)(col0 + r) * 256 + bOff + ch * 8, 16u);
        }
        CP_COMMIT();
    };

    prefetch(0);
    prefetch(1);
    #pragma unroll 1
    for (int kt = 0; kt < NKT; kt++) {
        CP_WAIT1();            // groups <= kt complete
        __syncthreads();       // buffer kt visible; buffer (kt+2)%3 free to overwrite
        if (kt + 2 < NKT) prefetch(kt + 2);
        else CP_COMMIT();      // empty group keeps wait-count invariant
        int buf = kt % 3;
        #pragma unroll
        for (int ks = 0; ks < 32; ks += 16) {
            uint32_t a[4][4], b[4][2];
            #pragma unroll
            for (int mi = 0; mi < 4; mi++) {
                int r = wm * 64 + mi * 16 + (lane & 15);
                int c = ks + (lane >> 4) * 8;
                ldm_x4(a[mi][0], a[mi][1], a[mi][2], a[mi][3],
                       sA_base[buf] + (uint32_t)(r * SPITCH + c) * 2);
            }
            #pragma unroll
            for (int nip = 0; nip < 2; nip++) {   // covers ni = 2*nip, 2*nip+1
                int m = lane >> 3;
                int r = wn * 32 + nip * 16 + (m >> 1) * 8 + (lane & 7);
                int c = ks + (m & 1) * 8;
                ldm_x4(b[2 * nip][0], b[2 * nip][1], b[2 * nip + 1][0], b[2 * nip + 1][1],
                       sB_base[buf] + (uint32_t)(r * SPITCH + c) * 2);
            }
            #pragma unroll
            for (int mi = 0; mi < 4; mi++)
                #pragma unroll
                for (int ni = 0; ni < 4; ni++)
                    mma_bf16(acc[mi][ni], a[mi], b[ni]);
        }
    }

    // epilogue: bias + optional silu, direct float2 stores
    #pragma unroll
    for (int ni = 0; ni < 4; ni++) {
        int n = col0 + wn * 32 + ni * 8 + (lane & 3) * 2;
        float b0 = bias[n], b1 = bias[n + 1];
        #pragma unroll
        for (int mi = 0; mi < 4; mi++) {
            int m = row0 + wm * 64 + mi * 16 + (lane >> 2);
            float v0 = acc[mi][ni][0] + b0;
            float v1 = acc[mi][ni][1] + b1;
            float v2 = acc[mi][ni][2] + b0;
            float v3 = acc[mi][ni][3] + b1;
            if (act) {
                v0 = v0 / (1.f + __expf(-v0));
                v1 = v1 / (1.f + __expf(-v1));
                v2 = v2 / (1.f + __expf(-v2));
                v3 = v3 / (1.f + __expf(-v3));
            }
            if (m < M)     *(float2*)(C + (size_t)m * Nn + n)       = make_float2(v0, v1);
            if (m + 8 < M) *(float2*)(C + (size_t)(m + 8) * Nn + n) = make_float2(v2, v3);
        }
    }
}

// ---------------- fused edge kernel: one warp per edge, float4 + red.v4 ----------------
__global__ __launch_bounds__(256) void edge_kernel(const int* __restrict__ ei,
                                                   const float* __restrict__ r_ij,
                                                   const float* __restrict__ d_ij,
                                                   const float* __restrict__ vec) {
    int gw = (blockIdx.x * blockDim.x + threadIdx.x) >> 5;
    if (gw >= EE) return;
    int lane = threadIdx.x & 31;
    int e = gw;
    int src = ei[e];
    int dst = ei[EE + e];

    float4 q  = ((const float4*)(g_qkv + (size_t)dst * 640))[lane];
    float4 kk = ((const float4*)(g_qkv + (size_t)src * 640 + 128))[lane];
    float4 dk = ((const float4*)(g_dkdv + (size_t)e * 512))[lane];
    float p = q.x * kk.x * dk.x + q.y * kk.y * dk.y + q.z * kk.z * dk.z + q.w * kk.w * dk.w;
    p += __shfl_xor_sync(0xffffffffu, p, 1);
    p += __shfl_xor_sync(0xffffffffu, p, 2);
    float attn = p / (1.f + __expf(-p));
    float r = r_ij[e];
    float cut = (r < 6.0f) ? 0.5f * (__cosf(r * 0.52359877559829887f) + 1.f) : 0.f;
    attn *= cut;

    int h = lane >> 2;
    int d4 = (lane & 3) * 4;
    const float* vb  = g_qkv  + (size_t)src * 640 + 256 + h * 48 + d4;
    const float* dvb = g_dkdv + (size_t)e * 512 + 128 + h * 48 + d4;
    float4 v0 = *(const float4*)vb;
    float4 v1 = *(const float4*)(vb + 16);
    float4 v2 = *(const float4*)(vb + 32);
    float4 w0 = *(const float4*)dvb;
    float4 w1 = *(const float4*)(dvb + 16);
    float4 w2 = *(const float4*)(dvb + 32);

    float4 xm  = make_float4(v0.x * w0.x * attn, v0.y * w0.y * attn,
                             v0.z * w0.z * attn, v0.w * w0.w * attn);
    float4 v1m = make_float4(v1.x * w1.x, v1.y * w1.y, v1.z * w1.z, v1.w * w1.w);
    float4 v2m = make_float4(v2.x * w2.x, v2.y * w2.y, v2.z * w2.z, v2.w * w2.w);

    red_add_v4(g_xagg + (size_t)dst * FF + lane * 4, xm);

    float dsx = d_ij[(size_t)e * 3 + 0];
    float dsy = d_ij[(size_t)e * 3 + 1];
    float dsz = d_ij[(size_t)e * 3 + 2];
    float ds[3] = {dsx, dsy, dsz};
    #pragma unroll
    for (int s = 0; s < 3; s++) {
        float4 vv = ((const float4*)(vec + (size_t)src * 384 + s * 128))[lane];
        float4 vm = make_float4(vv.x * v1m.x + v2m.x * ds[s],
                                vv.y * v1m.y + v2m.y * ds[s],
                                vv.z * v1m.z + v2m.z * ds[s],
                                vv.w * v1m.w + v2m.w * ds[s]);
        red_add_v4(g_vagg + (size_t)dst * 384 + s * 128 + lane * 4, vm);
    }
}

// ---------------- final epilogue ----------------
__global__ void final_kernel(float* __restrict__ out) {
    int n = blockIdx.x;
    int f = threadIdx.x;  // 128
    size_t ob = (size_t)n * 384;
    float o1 = g_o[ob + f], o2 = g_o[ob + 128 + f], o3 = g_o[ob + 256 + f];
    size_t vb = (size_t)n * 1152;
    float vd = 0.f;
    #pragma unroll
    for (int s = 0; s < 3; s++)
        vd += g_vp[vb + s * 384 + f] * g_vp[vb + s * 384 + 128 + f];
    out[(size_t)n * FF + f] = vd * o2 + o3;
    #pragma unroll
    for (int s = 0; s < 3; s++) {
        float v3 = g_vp[vb + s * 384 + 256 + f];
        out[(size_t)NN * FF + ((size_t)n * 3 + s) * FF + f] =
            v3 * o1 + g_vagg[((size_t)n * 3 + s) * FF + f];
    }
}

// ---------------- launch ----------------
extern "C" void kernel_launch(void* const* d_in, const int* in_sizes, int n_in,
                              void* d_out, int out_size) {
    const float* x    = (const float*)d_in[0];
    const float* vec  = (const float*)d_in[1];
    const int*   ei   = (const int*)d_in[2];
    const float* r_ij = (const float*)d_in[3];
    const float* f_ij = (const float*)d_in[4];
    const float* d_ij = (const float*)d_in[5];
    const float* ln_w = (const float*)d_in[6];
    const float* ln_b = (const float*)d_in[7];
    const float* Wq   = (const float*)d_in[8];
    const float* bq   = (const float*)d_in[9];
    const float* Wk   = (const float*)d_in[10];
    const float* bk   = (const float*)d_in[11];
    const float* Wv   = (const float*)d_in[12];
    const float* bv   = (const float*)d_in[13];
    const float* Wvec = (const float*)d_in[14];
    const float* bvec = (const float*)d_in[15];
    const float* Wo   = (const float*)d_in[16];
    const float* bo   = (const float*)d_in[17];
    const float* Wdk  = (const float*)d_in[18];
    const float* bdk  = (const float*)d_in[19];
    const float* Wdv  = (const float*)d_in[20];
    const float* bdv  = (const float*)d_in[21];
    float* out = (float*)d_out;

    void *pqkv, *pvp, *pdkdv, *pxagg, *pvagg, *po, *pbqkv, *pbdkv;
    void *pxn2, *pvec2, *pfij2, *pxagg2, *pWqkv2, *pWvec2, *pWdkv2, *pWo2;
    cudaGetSymbolAddress(&pqkv, g_qkv);
    cudaGetSymbolAddress(&pvp, g_vp);
    cudaGetSymbolAddress(&pdkdv, g_dkdv);
    cudaGetSymbolAddress(&pxagg, g_xagg);
    cudaGetSymbolAddress(&pvagg, g_vagg);
    cudaGetSymbolAddress(&po, g_o);
    cudaGetSymbolAddress(&pbqkv, g_bqkv);
    cudaGetSymbolAddress(&pbdkv, g_bdkv);
    cudaGetSymbolAddress(&pxn2, g_xn2);
    cudaGetSymbolAddress(&pvec2, g_vec2);
    cudaGetSymbolAddress(&pfij2, g_fij2);
    cudaGetSymbolAddress(&pxagg2, g_xagg2);
    cudaGetSymbolAddress(&pWqkv2, g_Wqkv2);
    cudaGetSymbolAddress(&pWvec2, g_Wvec2);
    cudaGetSymbolAddress(&pWdkv2, g_Wdkv2);
    cudaGetSymbolAddress(&pWo2, g_Wo2);

    cudaFuncSetAttribute(hmma_gemm, cudaFuncAttributeMaxDynamicSharedMemorySize, HMMA_SMEM);

    // 0. fused weight prep (concat + hi/lo)
    prep_all<<<(640 * 128 + 255) / 256, 256>>>(Wq, Wk, Wv, bq, bk, bv,
                                               Wdk, Wdv, bdk, bdv, Wvec, Wo);
    // 1. LayerNorm (writes hi/lo directly)
    ln_kernel<<<NN, 128>>>(x, ln_w, ln_b);
    // 2-3. activation conversions
    cvt_hilo<<<(3 * NN * 128 + 255) / 256, 256>>>(vec, (__nv_bfloat16*)pvec2, 3 * NN, 128);
    cvt_hilo<<<((size_t)EE * 128 + 255) / 256, 256>>>(f_ij, (__nv_bfloat16*)pfij2, EE, RBFN);
    // 4. qkv = xn @ Wqkv^T  (50000 x 640)
    {
        dim3 grid(640 / 128, (NN + 127) / 128);
        hmma_gemm<<<grid, 256, HMMA_SMEM>>>((const __nv_bfloat16*)pxn2,
                                            (const __nv_bfloat16*)pWqkv2,
                                            (const float*)pbqkv, (float*)pqkv, NN, 640, 0);
    }
    // 5. vp = vec @ Wvec^T  (150000 x 384)   <-- ncu -s 5 captures this launch
    {
        dim3 grid(384 / 128, (3 * NN + 127) / 128);
        hmma_gemm<<<grid, 256, HMMA_SMEM>>>((const __nv_bfloat16*)pvec2,
                                            (const __nv_bfloat16*)pWvec2,
                                            bvec, (float*)pvp, 3 * NN, 384, 0);
    }
    // 6. dkdv = silu(f_ij @ Wdkv^T)  (400000 x 512)
    {
        dim3 grid(512 / 128, EE / 128);
        hmma_gemm<<<grid, 256, HMMA_SMEM>>>((const __nv_bfloat16*)pfij2,
                                            (const __nv_bfloat16*)pWdkv2,
                                            (const float*)pbdkv, (float*)pdkdv, EE, 512, 1);
    }
    // 7. zero aggregation buffers
    cudaMemsetAsync(pxagg, 0, (size_t)NN * FF * sizeof(float));
    cudaMemsetAsync(pvagg, 0, (size_t)NN * 384 * sizeof(float));
    // 8. edge message + scatter
    edge_kernel<<<EE / 8, 256>>>(ei, r_ij, d_ij, vec);
    // 9. convert x_agg, then o = x_agg @ Wo^T  (50000 x 384)
    cvt_hilo<<<(NN * 128 + 255) / 256, 256>>>((const float*)pxagg, (__nv_bfloat16*)pxagg2, NN, 128);
    {
        dim3 grid(384 / 128, (NN + 127) / 128);
        hmma_gemm<<<grid, 256, HMMA_SMEM>>>((const __nv_bfloat16*)pxagg2,
                                            (const __nv_bfloat16*)pWo2,
                                            bo, (float*)po, NN, 384, 0);
    }
    // 10. epilogue
    final_kernel<<<NN, 128>>>(out);
}

// round 7
// speedup vs baseline: 2.1403x; 1.0899x over previous
#include <cuda_runtime.h>
#include <cuda_bf16.h>
#include <cstdint>

#define NN 50000
#define EE 400000
#define FF 128
#define RBFN 100

// ---------------- scratch (static device allocations; no cudaMalloc) ----------------
__device__ float g_qkv[(size_t)NN * 640];        // [q(128) | k(128) | v(384)]
__device__ float g_vp[(size_t)NN * 3 * 384];
__device__ float g_dkdv[(size_t)EE * 512];       // [dk(128) | dv(384)]
__device__ float g_xagg[(size_t)NN * FF];
__device__ float g_vagg[(size_t)NN * 384];
__device__ float g_o[(size_t)NN * 384];
__device__ float g_bqkv[640];
__device__ float g_bdkv[512];
__device__ int   g_hist[NN];
__device__ int   g_cursor[NN];
__device__ int   g_perm[EE];
// bf16 hi/lo split buffers: [R, 256] = [hi(128) | lo(128)]
__device__ __nv_bfloat16 g_xn2[(size_t)NN * 256];
__device__ __nv_bfloat16 g_vec2[(size_t)3 * NN * 256];
__device__ __nv_bfloat16 g_fij2[(size_t)EE * 256];
__device__ __nv_bfloat16 g_xagg2[(size_t)NN * 256];
__device__ __nv_bfloat16 g_Wqkv2[640 * 256];
__device__ __nv_bfloat16 g_Wvec2[384 * 256];
__device__ __nv_bfloat16 g_Wdkv2[512 * 256];
__device__ __nv_bfloat16 g_Wo2[384 * 256];

// ---------------- helpers ----------------
__device__ __forceinline__ uint32_t smem_u32(const void* p) {
    uint32_t a;
    asm("{ .reg .u64 t; cvta.to.shared.u64 t, %1; cvt.u32.u64 %0, t; }" : "=r"(a) : "l"(p));
    return a;
}
__device__ __forceinline__ void cp_async16(uint32_t dst, const void* src, uint32_t src_bytes) {
    asm volatile("cp.async.cg.shared.global [%0], [%1], 16, %2;"
                 :: "r"(dst), "l"(src), "r"(src_bytes) : "memory");
}
#define CP_COMMIT() asm volatile("cp.async.commit_group;" ::: "memory")
#define CP_WAIT1()  asm volatile("cp.async.wait_group 1;" ::: "memory")

__device__ __forceinline__ void ldm_x4(uint32_t& r0, uint32_t& r1, uint32_t& r2, uint32_t& r3,
                                       uint32_t addr) {
    asm volatile("ldmatrix.sync.aligned.m8n8.x4.shared.b16 {%0,%1,%2,%3}, [%4];"
                 : "=r"(r0), "=r"(r1), "=r"(r2), "=r"(r3) : "r"(addr));
}
__device__ __forceinline__ void mma_bf16(float* c, const uint32_t* a, const uint32_t* b) {
    asm volatile("mma.sync.aligned.m16n8k16.row.col.f32.bf16.bf16.f32 "
                 "{%0,%1,%2,%3}, {%4,%5,%6,%7}, {%8,%9}, {%0,%1,%2,%3};"
                 : "+f"(c[0]), "+f"(c[1]), "+f"(c[2]), "+f"(c[3])
                 : "r"(a[0]), "r"(a[1]), "r"(a[2]), "r"(a[3]), "r"(b[0]), "r"(b[1]));
}
__device__ __forceinline__ void red_add_v4(float* p, float4 v) {
    asm volatile("red.global.add.v4.f32 [%0], {%1, %2, %3, %4};"
                 :: "l"(p), "f"(v.x), "f"(v.y), "f"(v.z), "f"(v.w) : "memory");
}
__device__ __forceinline__ uint32_t pack_bf16x2(float a, float b) {
    __nv_bfloat162 t = __floats2bfloat162_rn(a, b);
    return *(uint32_t*)&t;
}
__device__ __forceinline__ void wr_hilo(__nv_bfloat16* dst, size_t row, int col, float v) {
    __nv_bfloat16 hi = __float2bfloat16(v);
    float lo = v - __bfloat162float(hi);
    dst[row * 256 + col] = hi;
    dst[row * 256 + 128 + col] = __float2bfloat16(lo);
}
__device__ __forceinline__ float bf_hi(float v) { return __bfloat162float(__float2bfloat16(v)); }

// ---------------- fused weight prep: concat + hi/lo split ----------------
__global__ void prep_all(const float* __restrict__ Wq, const float* __restrict__ Wk,
                         const float* __restrict__ Wv, const float* __restrict__ bq,
                         const float* __restrict__ bk, const float* __restrict__ bv,
                         const float* __restrict__ Wdk, const float* __restrict__ Wdv,
                         const float* __restrict__ bdk, const float* __restrict__ bdv,
                         const float* __restrict__ Wvec, const float* __restrict__ Wo) {
    int i = blockIdx.x * blockDim.x + threadIdx.x;
    int r = i >> 7, c = i & 127;
    if (i < 640 * 128) {
        float v = (r < 128) ? Wq[r * 128 + c]
                : (r < 256) ? Wk[(r - 128) * 128 + c]
                            : Wv[(r - 256) * 128 + c];
        wr_hilo(g_Wqkv2, r, c, v);
    }
    if (i < 512 * 128) {
        float v = (c < RBFN) ? ((r < 128) ? Wdk[r * RBFN + c] : Wdv[(r - 128) * RBFN + c]) : 0.f;
        wr_hilo(g_Wdkv2, r, c, v);
    }
    if (i < 384 * 128) {
        wr_hilo(g_Wvec2, r, c, Wvec[r * 128 + c]);
        wr_hilo(g_Wo2, r, c, Wo[r * 128 + c]);
    }
    if (i < 640)
        g_bqkv[i] = (i < 128) ? bq[i] : (i < 256) ? bk[i - 128] : bv[i - 256];
    if (i < 512)
        g_bdkv[i] = (i < 128) ? bdk[i] : bdv[i - 128];
}

// ---------------- vectorized cvt: K=128 rows, warp-per-row ----------------
__global__ __launch_bounds__(256) void cvt128(const float* __restrict__ src,
                                              __nv_bfloat16* __restrict__ dst, int R) {
    int gw = (blockIdx.x * blockDim.x + threadIdx.x) >> 5;
    int lane = threadIdx.x & 31;
    if (gw >= R) return;
    float4 v = ((const float4*)(src + (size_t)gw * 128))[lane];
    float hx = bf_hi(v.x), hy = bf_hi(v.y), hz = bf_hi(v.z), hw = bf_hi(v.w);
    uint2 hi = make_uint2(pack_bf16x2(v.x, v.y), pack_bf16x2(v.z, v.w));
    uint2 lo = make_uint2(pack_bf16x2(v.x - hx, v.y - hy), pack_bf16x2(v.z - hz, v.w - hw));
    uint2* o = (uint2*)(dst + (size_t)gw * 256);
    o[lane] = hi;
    o[32 + lane] = lo;
}

// ---------------- vectorized cvt: K=100 rows (f_ij), warp-per-row, zero-pad to 128 ----
__global__ __launch_bounds__(256) void cvt100(const float* __restrict__ src,
                                              __nv_bfloat16* __restrict__ dst, int R) {
    int gw = (blockIdx.x * blockDim.x + threadIdx.x) >> 5;
    int lane = threadIdx.x & 31;
    if (gw >= R) return;
    float4 v = make_float4(0.f, 0.f, 0.f, 0.f);
    if (lane < 25) v = *(const float4*)(src + (size_t)gw * 100 + lane * 4);
    float hx = bf_hi(v.x), hy = bf_hi(v.y), hz = bf_hi(v.z), hw = bf_hi(v.w);
    uint2 hi = make_uint2(pack_bf16x2(v.x, v.y), pack_bf16x2(v.z, v.w));
    uint2 lo = make_uint2(pack_bf16x2(v.x - hx, v.y - hy), pack_bf16x2(v.z - hz, v.w - hw));
    uint2* o = (uint2*)(dst + (size_t)gw * 256);
    o[lane] = hi;
    o[32 + lane] = lo;
}

// ---------------- LayerNorm (fused hi/lo output) ----------------
__global__ void ln_kernel(const float* __restrict__ x, const float* __restrict__ w,
                          const float* __restrict__ b) {
    int n = blockIdx.x;
    int f = threadIdx.x;  // 128 threads
    float v = x[(size_t)n * FF + f];
    __shared__ float red1[4], red2[4];
    float s = v;
    #pragma unroll
    for (int o = 16; o > 0; o >>= 1) s += __shfl_xor_sync(0xffffffffu, s, o);
    if ((f & 31) == 0) red1[f >> 5] = s;
    __syncthreads();
    float mean = (red1[0] + red1[1] + red1[2] + red1[3]) * (1.0f / FF);
    float c = v - mean;
    float s2 = c * c;
    #pragma unroll
    for (int o = 16; o > 0; o >>= 1) s2 += __shfl_xor_sync(0xffffffffu, s2, o);
    if ((f & 31) == 0) red2[f >> 5] = s2;
    __syncthreads();
    float var = (red2[0] + red2[1] + red2[2] + red2[3]) * (1.0f / FF);
    float y = c * rsqrtf(var + 1e-5f) * w[f] + b[f];
    wr_hilo(g_xn2, n, f, y);
}

// ---------------- counting sort by dst ----------------
__global__ void hist_kernel(const int* __restrict__ ei) {
    int i = blockIdx.x * blockDim.x + threadIdx.x;
    if (i < EE) atomicAdd(&g_hist[ei[EE + i]], 1);
}
__global__ __launch_bounds__(1024) void scan_kernel() {
    __shared__ int wsum[32];
    __shared__ int carry;
    int tid = threadIdx.x, lane = tid & 31, wid = tid >> 5;
    if (tid == 0) carry = 0;
    __syncthreads();
    for (int c = 0; c < NN; c += 1024) {
        int idx = c + tid;
        int v = (idx < NN) ? g_hist[idx] : 0;
        int x = v;
        #pragma unroll
        for (int o = 1; o < 32; o <<= 1) {
            int t = __shfl_up_sync(0xffffffffu, x, o);
            if (lane >= o) x += t;
        }
        if (lane == 31) wsum[wid] = x;
        __syncthreads();
        if (wid == 0) {
            int s = wsum[lane];
            #pragma unroll
            for (int o = 1; o < 32; o <<= 1) {
                int t = __shfl_up_sync(0xffffffffu, s, o);
                if (lane >= o) s += t;
            }
            wsum[lane] = s;
        }
        __syncthreads();
        int excl = carry + (wid ? wsum[wid - 1] : 0) + x - v;
        if (idx < NN) g_cursor[idx] = excl;
        __syncthreads();
        if (tid == 0) carry += wsum[31];
        __syncthreads();
    }
}
__global__ void scatter_kernel(const int* __restrict__ ei) {
    int i = blockIdx.x * blockDim.x + threadIdx.x;
    if (i >= EE) return;
    int d = ei[EE + i];
    int pos = atomicAdd(&g_cursor[d], 1);
    g_perm[pos] = i;
}

// ---------------- HMMA bf16 GEMM v3 (3-stage, 3-term hi/lo) ----------------
#define SPITCH 40
#define NKT 12
#define STAGE_BYTES (128 * SPITCH * 2)
#define HMMA_SMEM (3 * 2 * STAGE_BYTES)

__global__ __launch_bounds__(256, 2) void hmma_gemm(
    const __nv_bfloat16* __restrict__ A2, const __nv_bfloat16* __restrict__ B2,
    const float* __restrict__ bias, float* __restrict__ C, int M, int Nn, int act) {
    extern __shared__ char dynsmem[];

    int tid = threadIdx.x;
    int wid = tid >> 5, lane = tid & 31;
    int wm = wid & 1, wn = wid >> 1;
    int row0 = blockIdx.y * 128;
    int col0 = blockIdx.x * 128;

    uint32_t sA_base[3], sB_base[3];
    #pragma unroll
    for (int s = 0; s < 3; s++) {
        sA_base[s] = smem_u32(dynsmem + s * 2 * STAGE_BYTES);
        sB_base[s] = sA_base[s] + STAGE_BYTES;
    }

    float acc[4][4][4];
    #pragma unroll
    for (int i = 0; i < 4; i++)
        #pragma unroll
        for (int j = 0; j < 4; j++)
            #pragma unroll
            for (int k = 0; k < 4; k++) acc[i][j][k] = 0.f;

    auto prefetch = [&](int kt) {
        int buf = kt % 3;
        int aOff = ((kt >= 4 && kt < 8) ? 128 : 0) + (kt & 3) * 32;
        int bOff = ((kt >= 8) ? 128 : 0) + (kt & 3) * 32;
        #pragma unroll
        for (int i = 0; i < 2; i++) {
            int idx = tid + i * 256;
            int r = idx >> 2;
            int ch = idx & 3;
            uint32_t soff = (uint32_t)(r * SPITCH + ch * 8) * 2;
            uint32_t valid = (row0 + r < M) ? 16u : 0u;
            cp_async16(sA_base[buf] + soff,
                       A2 + (size_t)(row0 + r) * 256 + aOff + ch * 8, valid);
            cp_async16(sB_base[buf] + soff,
                       B2 + (size_t)(col0 + r) * 256 + bOff + ch * 8, 16u);
        }
        CP_COMMIT();
    };

    prefetch(0);
    prefetch(1);
    #pragma unroll 1
    for (int kt = 0; kt < NKT; kt++) {
        CP_WAIT1();
        __syncthreads();
        if (kt + 2 < NKT) prefetch(kt + 2);
        else CP_COMMIT();
        int buf = kt % 3;
        #pragma unroll
        for (int ks = 0; ks < 32; ks += 16) {
            uint32_t a[4][4], b[4][2];
            #pragma unroll
            for (int mi = 0; mi < 4; mi++) {
                int r = wm * 64 + mi * 16 + (lane & 15);
                int c = ks + (lane >> 4) * 8;
                ldm_x4(a[mi][0], a[mi][1], a[mi][2], a[mi][3],
                       sA_base[buf] + (uint32_t)(r * SPITCH + c) * 2);
            }
            #pragma unroll
            for (int nip = 0; nip < 2; nip++) {
                int m = lane >> 3;
                int r = wn * 32 + nip * 16 + (m >> 1) * 8 + (lane & 7);
                int c = ks + (m & 1) * 8;
                ldm_x4(b[2 * nip][0], b[2 * nip][1], b[2 * nip + 1][0], b[2 * nip + 1][1],
                       sB_base[buf] + (uint32_t)(r * SPITCH + c) * 2);
            }
            #pragma unroll
            for (int mi = 0; mi < 4; mi++)
                #pragma unroll
                for (int ni = 0; ni < 4; ni++)
                    mma_bf16(acc[mi][ni], a[mi], b[ni]);
        }
    }

    #pragma unroll
    for (int ni = 0; ni < 4; ni++) {
        int n = col0 + wn * 32 + ni * 8 + (lane & 3) * 2;
        float b0 = bias[n], b1 = bias[n + 1];
        #pragma unroll
        for (int mi = 0; mi < 4; mi++) {
            int m = row0 + wm * 64 + mi * 16 + (lane >> 2);
            float v0 = acc[mi][ni][0] + b0;
            float v1 = acc[mi][ni][1] + b1;
            float v2 = acc[mi][ni][2] + b0;
            float v3 = acc[mi][ni][3] + b1;
            if (act) {
                v0 = v0 / (1.f + __expf(-v0));
                v1 = v1 / (1.f + __expf(-v1));
                v2 = v2 / (1.f + __expf(-v2));
                v3 = v3 / (1.f + __expf(-v3));
            }
            if (m < M)     *(float2*)(C + (size_t)m * Nn + n)       = make_float2(v0, v1);
            if (m + 8 < M) *(float2*)(C + (size_t)(m + 8) * Nn + n) = make_float2(v2, v3);
        }
    }
}

// ---------------- edge kernel v3: dst-sorted, warp per 8 edges, register accumulation --
#define CHUNK 8
__global__ __launch_bounds__(256) void edge_kernel(const int* __restrict__ ei,
                                                   const float* __restrict__ r_ij,
                                                   const float* __restrict__ d_ij,
                                                   const float* __restrict__ vec) {
    int gw = (blockIdx.x * blockDim.x + threadIdx.x) >> 5;
    int lane = threadIdx.x & 31;
    size_t base = (size_t)gw * CHUNK;
    if (base >= EE) return;
    int nmax = (int)(((size_t)EE - base) < CHUNK ? (EE - base) : CHUNK);

    int h = lane >> 2;
    int d4 = (lane & 3) * 4;
    int prev = -1;
    float4 q = make_float4(0.f, 0.f, 0.f, 0.f);
    float4 ax  = make_float4(0.f, 0.f, 0.f, 0.f);
    float4 av0 = ax, av1 = ax, av2 = ax;

    for (int i = 0; i < nmax; i++) {
        int e = g_perm[base + i];
        int src = ei[e];
        int dst = ei[EE + e];
        if (dst != prev) {
            if (prev >= 0) {
                red_add_v4(g_xagg + (size_t)prev * FF + lane * 4, ax);
                red_add_v4(g_vagg + (size_t)prev * 384 +       lane * 4, av0);
                red_add_v4(g_vagg + (size_t)prev * 384 + 128 + lane * 4, av1);
                red_add_v4(g_vagg + (size_t)prev * 384 + 256 + lane * 4, av2);
            }
            ax = av0 = av1 = av2 = make_float4(0.f, 0.f, 0.f, 0.f);
            q = ((const float4*)(g_qkv + (size_t)dst * 640))[lane];
            prev = dst;
        }
        float4 kk = ((const float4*)(g_qkv + (size_t)src * 640 + 128))[lane];
        float4 dk = ((const float4*)(g_dkdv + (size_t)e * 512))[lane];
        float p = q.x * kk.x * dk.x + q.y * kk.y * dk.y + q.z * kk.z * dk.z + q.w * kk.w * dk.w;
        p += __shfl_xor_sync(0xffffffffu, p, 1);
        p += __shfl_xor_sync(0xffffffffu, p, 2);
        float attn = p / (1.f + __expf(-p));
        float r = r_ij[e];
        float cut = (r < 6.0f) ? 0.5f * (__cosf(r * 0.52359877559829887f) + 1.f) : 0.f;
        attn *= cut;

        const float* vb  = g_qkv  + (size_t)src * 640 + 256 + h * 48 + d4;
        const float* dvb = g_dkdv + (size_t)e * 512 + 128 + h * 48 + d4;
        float4 v0 = *(const float4*)vb;
        float4 v1 = *(const float4*)(vb + 16);
        float4 v2 = *(const float4*)(vb + 32);
        float4 w0 = *(const float4*)dvb;
        float4 w1 = *(const float4*)(dvb + 16);
        float4 w2 = *(const float4*)(dvb + 32);

        ax.x += v0.x * w0.x * attn; ax.y += v0.y * w0.y * attn;
        ax.z += v0.z * w0.z * attn; ax.w += v0.w * w0.w * attn;
        float4 v1m = make_float4(v1.x * w1.x, v1.y * w1.y, v1.z * w1.z, v1.w * w1.w);
        float4 v2m = make_float4(v2.x * w2.x, v2.y * w2.y, v2.z * w2.z, v2.w * w2.w);

        float dsx = d_ij[(size_t)e * 3 + 0];
        float dsy = d_ij[(size_t)e * 3 + 1];
        float dsz = d_ij[(size_t)e * 3 + 2];
        float4 vv0 = ((const float4*)(vec + (size_t)src * 384))[lane];
        float4 vv1 = ((const float4*)(vec + (size_t)src * 384 + 128))[lane];
        float4 vv2 = ((const float4*)(vec + (size_t)src * 384 + 256))[lane];
        av0.x += vv0.x * v1m.x + v2m.x * dsx; av0.y += vv0.y * v1m.y + v2m.y * dsx;
        av0.z += vv0.z * v1m.z + v2m.z * dsx; av0.w += vv0.w * v1m.w + v2m.w * dsx;
        av1.x += vv1.x * v1m.x + v2m.x * dsy; av1.y += vv1.y * v1m.y + v2m.y * dsy;
        av1.z += vv1.z * v1m.z + v2m.z * dsy; av1.w += vv1.w * v1m.w + v2m.w * dsy;
        av2.x += vv2.x * v1m.x + v2m.x * dsz; av2.y += vv2.y * v1m.y + v2m.y * dsz;
        av2.z += vv2.z * v1m.z + v2m.z * dsz; av2.w += vv2.w * v1m.w + v2m.w * dsz;
    }
    if (prev >= 0) {
        red_add_v4(g_xagg + (size_t)prev * FF + lane * 4, ax);
        red_add_v4(g_vagg + (size_t)prev * 384 +       lane * 4, av0);
        red_add_v4(g_vagg + (size_t)prev * 384 + 128 + lane * 4, av1);
        red_add_v4(g_vagg + (size_t)prev * 384 + 256 + lane * 4, av2);
    }
}

// ---------------- final epilogue ----------------
__global__ void final_kernel(float* __restrict__ out) {
    int n = blockIdx.x;
    int f = threadIdx.x;  // 128
    size_t ob = (size_t)n * 384;
    float o1 = g_o[ob + f], o2 = g_o[ob + 128 + f], o3 = g_o[ob + 256 + f];
    size_t vb = (size_t)n * 1152;
    float vd = 0.f;
    #pragma unroll
    for (int s = 0; s < 3; s++)
        vd += g_vp[vb + s * 384 + f] * g_vp[vb + s * 384 + 128 + f];
    out[(size_t)n * FF + f] = vd * o2 + o3;
    #pragma unroll
    for (int s = 0; s < 3; s++) {
        float v3 = g_vp[vb + s * 384 + 256 + f];
        out[(size_t)NN * FF + ((size_t)n * 3 + s) * FF + f] =
            v3 * o1 + g_vagg[((size_t)n * 3 + s) * FF + f];
    }
}

// ---------------- launch ----------------
extern "C" void kernel_launch(void* const* d_in, const int* in_sizes, int n_in,
                              void* d_out, int out_size) {
    const float* x    = (const float*)d_in[0];
    const float* vec  = (const float*)d_in[1];
    const int*   ei   = (const int*)d_in[2];
    const float* r_ij = (const float*)d_in[3];
    const float* f_ij = (const float*)d_in[4];
    const float* d_ij = (const float*)d_in[5];
    const float* ln_w = (const float*)d_in[6];
    const float* ln_b = (const float*)d_in[7];
    const float* Wq   = (const float*)d_in[8];
    const float* bq   = (const float*)d_in[9];
    const float* Wk   = (const float*)d_in[10];
    const float* bk   = (const float*)d_in[11];
    const float* Wv   = (const float*)d_in[12];
    const float* bv   = (const float*)d_in[13];
    const float* Wvec = (const float*)d_in[14];
    const float* bvec = (const float*)d_in[15];
    const float* Wo   = (const float*)d_in[16];
    const float* bo   = (const float*)d_in[17];
    const float* Wdk  = (const float*)d_in[18];
    const float* bdk  = (const float*)d_in[19];
    const float* Wdv  = (const float*)d_in[20];
    const float* bdv  = (const float*)d_in[21];
    float* out = (float*)d_out;

    void *pqkv, *pvp, *pdkdv, *pxagg, *pvagg, *po, *pbqkv, *pbdkv, *phist;
    void *pxn2, *pvec2, *pfij2, *pxagg2, *pWqkv2, *pWvec2, *pWdkv2, *pWo2;
    cudaGetSymbolAddress(&pqkv, g_qkv);
    cudaGetSymbolAddress(&pvp, g_vp);
    cudaGetSymbolAddress(&pdkdv, g_dkdv);
    cudaGetSymbolAddress(&pxagg, g_xagg);
    cudaGetSymbolAddress(&pvagg, g_vagg);
    cudaGetSymbolAddress(&po, g_o);
    cudaGetSymbolAddress(&pbqkv, g_bqkv);
    cudaGetSymbolAddress(&pbdkv, g_bdkv);
    cudaGetSymbolAddress(&phist, g_hist);
    cudaGetSymbolAddress(&pxn2, g_xn2);
    cudaGetSymbolAddress(&pvec2, g_vec2);
    cudaGetSymbolAddress(&pfij2, g_fij2);
    cudaGetSymbolAddress(&pxagg2, g_xagg2);
    cudaGetSymbolAddress(&pWqkv2, g_Wqkv2);
    cudaGetSymbolAddress(&pWvec2, g_Wvec2);
    cudaGetSymbolAddress(&pWdkv2, g_Wdkv2);
    cudaGetSymbolAddress(&pWo2, g_Wo2);

    cudaFuncSetAttribute(hmma_gemm, cudaFuncAttributeMaxDynamicSharedMemorySize, HMMA_SMEM);

    // 0. fused weight prep
    prep_all<<<(640 * 128 + 255) / 256, 256>>>(Wq, Wk, Wv, bq, bk, bv,
                                               Wdk, Wdv, bdk, bdv, Wvec, Wo);
    // 1. counting sort by dst
    cudaMemsetAsync(phist, 0, NN * sizeof(int));
    hist_kernel<<<(EE + 255) / 256, 256>>>(ei);
    scan_kernel<<<1, 1024>>>();
    scatter_kernel<<<(EE + 255) / 256, 256>>>(ei);
    // 2. LayerNorm (writes hi/lo directly)
    ln_kernel<<<NN, 128>>>(x, ln_w, ln_b);
    // 3. activation conversions (vectorized, warp-per-row)
    cvt128<<<(3 * NN * 32 + 255) / 256, 256>>>(vec, (__nv_bfloat16*)pvec2, 3 * NN);
    cvt100<<<(EE * 32 + 255) / 256, 256>>>(f_ij, (__nv_bfloat16*)pfij2, EE);
    // 4. qkv = xn @ Wqkv^T  (50000 x 640)
    {
        dim3 grid(640 / 128, (NN + 127) / 128);
        hmma_gemm<<<grid, 256, HMMA_SMEM>>>((const __nv_bfloat16*)pxn2,
                                            (const __nv_bfloat16*)pWqkv2,
                                            (const float*)pbqkv, (float*)pqkv, NN, 640, 0);
    }
    // 5. vp = vec @ Wvec^T  (150000 x 384)
    {
        dim3 grid(384 / 128, (3 * NN + 127) / 128);
        hmma_gemm<<<grid, 256, HMMA_SMEM>>>((const __nv_bfloat16*)pvec2,
                                            (const __nv_bfloat16*)pWvec2,
                                            bvec, (float*)pvp, 3 * NN, 384, 0);
    }
    // 6. dkdv = silu(f_ij @ Wdkv^T)  (400000 x 512)
    {
        dim3 grid(512 / 128, EE / 128);
        hmma_gemm<<<grid, 256, HMMA_SMEM>>>((const __nv_bfloat16*)pfij2,
                                            (const __nv_bfloat16*)pWdkv2,
                                            (const float*)pbdkv, (float*)pdkdv, EE, 512, 1);
    }
    // 7. zero aggregation buffers
    cudaMemsetAsync(pxagg, 0, (size_t)NN * FF * sizeof(float));
    cudaMemsetAsync(pvagg, 0, (size_t)NN * 384 * sizeof(float));
    // 8. edge message + scatter (dst-sorted, register accumulation)
    {
        int warps = (EE + CHUNK - 1) / CHUNK;
        edge_kernel<<<(warps * 32 + 255) / 256, 256>>>(ei, r_ij, d_ij, vec);
    }
    // 9. convert x_agg, then o = x_agg @ Wo^T  (50000 x 384)
    cvt128<<<(NN * 32 + 255) / 256, 256>>>((const float*)pxagg, (__nv_bfloat16*)pxagg2, NN);
    {
        dim3 grid(384 / 128, (NN + 127) / 128);
        hmma_gemm<<<grid, 256, HMMA_SMEM>>>((const __nv_bfloat16*)pxagg2,
                                            (const __nv_bfloat16*)pWo2,
                                            bo, (float*)po, NN, 384, 0);
    }
    // 10. epilogue
    final_kernel<<<NN, 128>>>(out);
}